// round 1
// baseline (speedup 1.0000x reference)
#include <cuda_runtime.h>
#include <cuda_bf16.h>

// Problem constants
#define N_DRUG  10000
#define N_PROT  20000
#define DH      128          // D_IN == H == 128
#define N_EDGES 1000000
#define N_LAB   500000

// ---------------- scratch (device globals; no allocation allowed) ----------
__device__ float g_tD[N_DRUG * DH];   // drug-sized transform buffer (also uD)
__device__ float g_tP[N_PROT * DH];   // prot-sized transform buffer (also uP)
__device__ float g_rD[N_DRUG * DH];   // drug-sized residual buffer
__device__ float g_rP[N_PROT * DH];   // prot-sized residual buffer
__device__ float g_hD[N_DRUG * DH];   // hidden drug
__device__ float g_hP[N_PROT * DH];   // hidden prot

__device__ int g_cntP[N_PROT];
__device__ int g_cntD[N_DRUG];
__device__ int g_offP[N_PROT + 1];
__device__ int g_offD[N_DRUG + 1];
__device__ int g_posP[N_PROT];
__device__ int g_posD[N_DRUG];
__device__ int g_srcP[N_EDGES];       // CSR by ei_col: neighbor drug ids per protein
__device__ int g_srcD[N_EDGES];       // CSR by ei_row: neighbor prot ids per drug

// ---------------- CSR build ------------------------------------------------
__global__ void zero_counts_kernel() {
    int i = blockIdx.x * blockDim.x + threadIdx.x;
    if (i < N_PROT) g_cntP[i] = 0;
    if (i < N_DRUG) g_cntD[i] = 0;
}

__global__ void hist_kernel(const int* __restrict__ ei_row,
                            const int* __restrict__ ei_col, int n) {
    int i = blockIdx.x * blockDim.x + threadIdx.x;
    if (i < n) {
        atomicAdd(&g_cntP[ei_col[i]], 1);
        atomicAdd(&g_cntD[ei_row[i]], 1);
    }
}

// blockIdx.x == 0 -> protein arrays, == 1 -> drug arrays. 1024 threads.
__global__ void scan_kernel() {
    const int n  = (blockIdx.x == 0) ? N_PROT : N_DRUG;
    int* cnt     = (blockIdx.x == 0) ? g_cntP : g_cntD;
    int* off     = (blockIdx.x == 0) ? g_offP : g_offD;
    int* pos     = (blockIdx.x == 0) ? g_posP : g_posD;

    __shared__ int sums[1024];
    int tid = threadIdx.x;
    int chunk = (n + 1023) >> 10;
    int start = tid * chunk;
    int end   = start + chunk; if (end > n) end = n;
    if (start > n) start = n;

    int s = 0;
    for (int i = start; i < end; i++) s += cnt[i];
    sums[tid] = s;
    __syncthreads();
    for (int d = 1; d < 1024; d <<= 1) {
        int v = (tid >= d) ? sums[tid - d] : 0;
        __syncthreads();
        sums[tid] += v;
        __syncthreads();
    }
    int prefix = tid ? sums[tid - 1] : 0;
    for (int i = start; i < end; i++) {
        off[i] = prefix;
        pos[i] = prefix;
        prefix += cnt[i];
    }
    if (tid == 1023) off[n] = sums[1023];
}

__global__ void fill_kernel(const int* __restrict__ ei_row,
                            const int* __restrict__ ei_col, int n) {
    int i = blockIdx.x * blockDim.x + threadIdx.x;
    if (i < n) {
        int r = ei_row[i], c = ei_col[i];
        int p = atomicAdd(&g_posP[c], 1);
        g_srcP[p] = r;
        int q = atomicAdd(&g_posD[r], 1);
        g_srcD[q] = c;
    }
}

// ---------------- fused segment-sum + residual (+ReLU) ---------------------
// out[d] = (relu?)( sum_{j in N(d)} t[src[j]] + r[d] ), 1 warp per dst row.
__global__ void __launch_bounds__(256) seg_agg_kernel(
    const float* __restrict__ t, const float* __restrict__ r,
    const int* __restrict__ off, const int* __restrict__ src,
    float* __restrict__ out, int n_dst, int do_relu)
{
    int w    = (blockIdx.x * blockDim.x + threadIdx.x) >> 5;
    int lane = threadIdx.x & 31;
    if (w >= n_dst) return;

    int s = off[w], e = off[w + 1];
    const float4* t4 = (const float4*)t;
    float4 acc = ((const float4*)r)[w * 32 + lane];

    int i = s;
    for (; i + 2 <= e; i += 2) {
        int s0 = __ldg(src + i);
        int s1 = __ldg(src + i + 1);
        float4 v0 = t4[s0 * 32 + lane];
        float4 v1 = t4[s1 * 32 + lane];
        acc.x += v0.x + v1.x;
        acc.y += v0.y + v1.y;
        acc.z += v0.z + v1.z;
        acc.w += v0.w + v1.w;
    }
    if (i < e) {
        int s0 = __ldg(src + i);
        float4 v0 = t4[s0 * 32 + lane];
        acc.x += v0.x; acc.y += v0.y; acc.z += v0.z; acc.w += v0.w;
    }
    if (do_relu) {
        acc.x = fmaxf(acc.x, 0.f);
        acc.y = fmaxf(acc.y, 0.f);
        acc.z = fmaxf(acc.z, 0.f);
        acc.w = fmaxf(acc.w, 0.f);
    }
    ((float4*)out)[w * 32 + lane] = acc;
}

// ---------------- SGEMM: C = A[N,128] @ B[128,128] (+bias) -----------------
// blockIdx.y selects (B0,bias0,C0) or (B1,bias1,C1) so two weight matrices
// sharing the same A are computed in one launch.
#define BM 128
#define BN 128
#define BK 16

__global__ void __launch_bounds__(256) gemm_dual_kernel(
    const float* __restrict__ A, int N,
    const float* __restrict__ B0, const float* __restrict__ bias0, float* __restrict__ C0,
    const float* __restrict__ B1, const float* __restrict__ bias1, float* __restrict__ C1)
{
    const float* B;  const float* bias;  float* C;
    if (blockIdx.y == 0) { B = B0; bias = bias0; C = C0; }
    else                 { B = B1; bias = bias1; C = C1; }

    __shared__ float As[BK][BM + 4];
    __shared__ float Bs[BK][BN];

    int tid = threadIdx.x;
    int m0  = blockIdx.x * BM;
    int ty  = tid >> 4;   // 0..15
    int tx  = tid & 15;   // 0..15

    float acc[8][8];
    #pragma unroll
    for (int i = 0; i < 8; i++)
        #pragma unroll
        for (int j = 0; j < 8; j++) acc[i][j] = 0.f;

    for (int k0 = 0; k0 < 128; k0 += BK) {
        // load A tile (BM x BK) transposed into As[k][m]
        #pragma unroll
        for (int l = 0; l < 2; l++) {
            int f   = tid + l * 256;       // 0..511
            int row = f >> 2;              // 0..127
            int c4  = f & 3;               // 0..3
            int gr  = m0 + row;
            float4 v = make_float4(0.f, 0.f, 0.f, 0.f);
            if (gr < N) v = *(const float4*)(A + gr * 128 + k0 + c4 * 4);
            As[c4 * 4 + 0][row] = v.x;
            As[c4 * 4 + 1][row] = v.y;
            As[c4 * 4 + 2][row] = v.z;
            As[c4 * 4 + 3][row] = v.w;
        }
        // load B tile (BK x BN)
        #pragma unroll
        for (int l = 0; l < 2; l++) {
            int f  = tid + l * 256;
            int kr = f >> 5;               // 0..15
            int c4 = f & 31;               // 0..31
            float4 v = *(const float4*)(B + (k0 + kr) * 128 + c4 * 4);
            *(float4*)(&Bs[kr][c4 * 4]) = v;
        }
        __syncthreads();

        #pragma unroll
        for (int kk = 0; kk < BK; kk++) {
            float a[8], b[8];
            *(float4*)(a)     = *(const float4*)(&As[kk][ty * 8]);
            *(float4*)(a + 4) = *(const float4*)(&As[kk][ty * 8 + 4]);
            *(float4*)(b)     = *(const float4*)(&Bs[kk][tx * 8]);
            *(float4*)(b + 4) = *(const float4*)(&Bs[kk][tx * 8 + 4]);
            #pragma unroll
            for (int i = 0; i < 8; i++)
                #pragma unroll
                for (int j = 0; j < 8; j++)
                    acc[i][j] += a[i] * b[j];
        }
        __syncthreads();
    }

    float bv[8];
    #pragma unroll
    for (int j = 0; j < 8; j++) bv[j] = bias ? bias[tx * 8 + j] : 0.f;

    #pragma unroll
    for (int i = 0; i < 8; i++) {
        int gr = m0 + ty * 8 + i;
        if (gr < N) {
            float4 o0, o1;
            o0.x = acc[i][0] + bv[0]; o0.y = acc[i][1] + bv[1];
            o0.z = acc[i][2] + bv[2]; o0.w = acc[i][3] + bv[3];
            o1.x = acc[i][4] + bv[4]; o1.y = acc[i][5] + bv[5];
            o1.z = acc[i][6] + bv[6]; o1.w = acc[i][7] + bv[7];
            *(float4*)(C + gr * 128 + tx * 8)     = o0;
            *(float4*)(C + gr * 128 + tx * 8 + 4) = o1;
        }
    }
}

// ---------------- decoder: out[l] = relu(uD[r]+uP[c]+bd1) . Wd2 + bd2 ------
__global__ void __launch_bounds__(256) decoder_kernel(
    const float* __restrict__ uD, const float* __restrict__ uP,
    const int* __restrict__ el_row, const int* __restrict__ el_col,
    const float* __restrict__ bd1, const float* __restrict__ Wd2,
    const float* __restrict__ bd2, float* __restrict__ out, int L)
{
    int w    = (blockIdx.x * blockDim.x + threadIdx.x) >> 5;
    int lane = threadIdx.x & 31;
    if (w >= L) return;

    int r = __ldg(el_row + w);
    int c = __ldg(el_col + w);
    float4 a  = ((const float4*)uD)[r * 32 + lane];
    float4 b  = ((const float4*)uP)[c * 32 + lane];
    float4 bb = ((const float4*)bd1)[lane];
    float4 w2 = ((const float4*)Wd2)[lane];

    float h0 = fmaxf(a.x + b.x + bb.x, 0.f);
    float h1 = fmaxf(a.y + b.y + bb.y, 0.f);
    float h2 = fmaxf(a.z + b.z + bb.z, 0.f);
    float h3 = fmaxf(a.w + b.w + bb.w, 0.f);

    float p = h0 * w2.x + h1 * w2.y + h2 * w2.z + h3 * w2.w;
    #pragma unroll
    for (int o = 16; o; o >>= 1) p += __shfl_down_sync(0xFFFFFFFFu, p, o);
    if (lane == 0) out[w] = p + __ldg(bd2);
}

// ---------------- launch ----------------------------------------------------
extern "C" void kernel_launch(void* const* d_in, const int* in_sizes, int n_in,
                              void* d_out, int out_size)
{
    const float* x_drug  = (const float*)d_in[0];
    const float* x_prot  = (const float*)d_in[1];
    const int*   ei_row  = (const int*)d_in[2];
    const int*   ei_col  = (const int*)d_in[3];
    const int*   el_row  = (const int*)d_in[4];
    const int*   el_col  = (const int*)d_in[5];
    const float* W1f_l   = (const float*)d_in[6];
    const float* b1f     = (const float*)d_in[7];
    const float* W1f_r   = (const float*)d_in[8];
    const float* W1r_l   = (const float*)d_in[9];
    const float* b1r     = (const float*)d_in[10];
    const float* W1r_r   = (const float*)d_in[11];
    const float* W2f_l   = (const float*)d_in[12];
    const float* b2f     = (const float*)d_in[13];
    const float* W2f_r   = (const float*)d_in[14];
    const float* W2r_l   = (const float*)d_in[15];
    const float* b2r     = (const float*)d_in[16];
    const float* W2r_r   = (const float*)d_in[17];
    const float* Wd1     = (const float*)d_in[18];
    const float* bd1     = (const float*)d_in[19];
    const float* Wd2     = (const float*)d_in[20];
    const float* bd2     = (const float*)d_in[21];

    const int nE = in_sizes[2];
    const int nL = in_sizes[4];

    float* outZd = (float*)d_out;                       // [N_DRUG,128]
    float* outZp = outZd + (size_t)N_DRUG * DH;         // [N_PROT,128]
    float* outO  = outZp + (size_t)N_PROT * DH;         // [N_LAB]

    // resolve scratch addresses (host-side immediate calls; not graph nodes)
    float *tD, *tP, *rD, *rP, *hD, *hP;
    cudaGetSymbolAddress((void**)&tD, g_tD);
    cudaGetSymbolAddress((void**)&tP, g_tP);
    cudaGetSymbolAddress((void**)&rD, g_rD);
    cudaGetSymbolAddress((void**)&rP, g_rP);
    cudaGetSymbolAddress((void**)&hD, g_hD);
    cudaGetSymbolAddress((void**)&hP, g_hP);
    int *offP, *offD, *srcP, *srcD;
    cudaGetSymbolAddress((void**)&offP, g_offP);
    cudaGetSymbolAddress((void**)&offD, g_offD);
    cudaGetSymbolAddress((void**)&srcP, g_srcP);
    cudaGetSymbolAddress((void**)&srcD, g_srcD);

    // ---- CSR build (reused by both layers) ----
    zero_counts_kernel<<<(N_PROT + 255) / 256, 256>>>();
    hist_kernel<<<(nE + 255) / 256, 256>>>(ei_row, ei_col, nE);
    scan_kernel<<<2, 1024>>>();
    fill_kernel<<<(nE + 255) / 256, 256>>>(ei_row, ei_col, nE);

    dim3 gD((N_DRUG + BM - 1) / BM, 2);
    dim3 gP((N_PROT + BM - 1) / BM, 2);
    dim3 gD1((N_DRUG + BM - 1) / BM, 1);
    dim3 gP1((N_PROT + BM - 1) / BM, 1);

    // ---- layer 1: transforms + residuals ----
    gemm_dual_kernel<<<gD, 256>>>(x_drug, N_DRUG,
                                  W1f_l, nullptr, tD,     // tD = x_drug @ W1f_l
                                  W1r_r, b1r,     rD);    // rD = x_drug @ W1r_r + b1r
    gemm_dual_kernel<<<gP, 256>>>(x_prot, N_PROT,
                                  W1r_l, nullptr, tP,     // tP = x_prot @ W1r_l
                                  W1f_r, b1f,     rP);    // rP = x_prot @ W1f_r + b1f

    // h_prot = relu(segsum_prot(tD) + rP); h_drug = relu(segsum_drug(tP) + rD)
    seg_agg_kernel<<<(N_PROT * 32 + 255) / 256, 256>>>(tD, rP, offP, srcP, hP, N_PROT, 1);
    seg_agg_kernel<<<(N_DRUG * 32 + 255) / 256, 256>>>(tP, rD, offD, srcD, hD, N_DRUG, 1);

    // ---- layer 2 ----
    gemm_dual_kernel<<<gD, 256>>>(hD, N_DRUG,
                                  W2f_l, nullptr, tD,
                                  W2r_r, b2r,     rD);
    gemm_dual_kernel<<<gP, 256>>>(hP, N_PROT,
                                  W2r_l, nullptr, tP,
                                  W2f_r, b2f,     rP);

    seg_agg_kernel<<<(N_PROT * 32 + 255) / 256, 256>>>(tD, rP, offP, srcP, outZp, N_PROT, 0);
    seg_agg_kernel<<<(N_DRUG * 32 + 255) / 256, 256>>>(tP, rD, offD, srcD, outZd, N_DRUG, 0);

    // ---- decoder: per-node transforms then per-edge MLP ----
    gemm_dual_kernel<<<gD1, 256>>>(outZd, N_DRUG,
                                   Wd1,            nullptr, tD,   // uD = z_drug @ Wd1[0:128]
                                   nullptr, nullptr, nullptr);
    gemm_dual_kernel<<<gP1, 256>>>(outZp, N_PROT,
                                   Wd1 + 128 * 128, nullptr, tP,  // uP = z_prot @ Wd1[128:256]
                                   nullptr, nullptr, nullptr);

    decoder_kernel<<<(nL * 32 + 255) / 256, 256>>>(tD, tP, el_row, el_col,
                                                   bd1, Wd2, bd2, outO, nL);
}

// round 2
// speedup vs baseline: 1.3786x; 1.3786x over previous
#include <cuda_runtime.h>
#include <cuda_fp16.h>

// Problem constants
#define N_DRUG  10000
#define N_PROT  20000
#define DH      128
#define N_EDGES 1000000
#define N_LAB   500000

// ---------------- scratch (device globals) ----------------------------------
__device__ float g_tD[N_DRUG * DH];   // half-precision transform buffer (cast)
__device__ float g_tP[N_PROT * DH];
__device__ float g_rD[N_DRUG * DH];   // fp32 residual
__device__ float g_rP[N_PROT * DH];
__device__ float g_hD[N_DRUG * DH];   // fp32 hidden
__device__ float g_hP[N_PROT * DH];

__device__ int g_cntP[N_PROT];
__device__ int g_cntD[N_DRUG];
__device__ int g_offP[N_PROT + 1];
__device__ int g_offD[N_DRUG + 1];
__device__ int g_rnkP[N_EDGES];
__device__ int g_rnkD[N_EDGES];
__device__ int g_srcP[N_EDGES];
__device__ int g_srcD[N_EDGES];

// ---------------- small helpers ---------------------------------------------
__device__ __forceinline__ unsigned long long pack2(float x, float y) {
    unsigned long long r;
    asm("mov.b64 %0, {%1, %2};" : "=l"(r) : "f"(x), "f"(y));
    return r;
}
__device__ __forceinline__ float2 unpack2(unsigned long long v) {
    float2 r;
    asm("mov.b64 {%0, %1}, %2;" : "=f"(r.x), "=f"(r.y) : "l"(v));
    return r;
}
__device__ __forceinline__ void ffma2(unsigned long long& d,
                                      unsigned long long a,
                                      unsigned long long b) {
    asm("fma.rn.f32x2 %0, %1, %2, %0;" : "+l"(d) : "l"(a), "l"(b));
}

// ---------------- CSR build --------------------------------------------------
__global__ void zero_counts_kernel() {
    int i = blockIdx.x * blockDim.x + threadIdx.x;
    if (i < N_PROT) g_cntP[i] = 0;
    if (i < N_DRUG) g_cntD[i] = 0;
}

__global__ void hist_kernel(const int* __restrict__ ei_row,
                            const int* __restrict__ ei_col, int n) {
    int i = blockIdx.x * blockDim.x + threadIdx.x;
    if (i < n) {
        int r = ei_row[i], c = ei_col[i];
        g_rnkP[i] = atomicAdd(&g_cntP[c], 1);
        g_rnkD[i] = atomicAdd(&g_cntD[r], 1);
    }
}

__global__ void scan_kernel() {
    const int n = (blockIdx.x == 0) ? N_PROT : N_DRUG;
    int* cnt    = (blockIdx.x == 0) ? g_cntP : g_cntD;
    int* off    = (blockIdx.x == 0) ? g_offP : g_offD;

    __shared__ int sums[1024];
    int tid = threadIdx.x;
    int chunk = (n + 1023) >> 10;
    int start = tid * chunk;
    int end = start + chunk; if (end > n) end = n;
    if (start > n) start = n;

    int s = 0;
    for (int i = start; i < end; i++) s += cnt[i];
    sums[tid] = s;
    __syncthreads();
    for (int d = 1; d < 1024; d <<= 1) {
        int v = (tid >= d) ? sums[tid - d] : 0;
        __syncthreads();
        sums[tid] += v;
        __syncthreads();
    }
    int prefix = tid ? sums[tid - 1] : 0;
    for (int i = start; i < end; i++) {
        off[i] = prefix;
        prefix += cnt[i];
    }
    if (tid == 1023) off[n] = sums[1023];
}

__global__ void fill_kernel(const int* __restrict__ ei_row,
                            const int* __restrict__ ei_col, int n) {
    int i = blockIdx.x * blockDim.x + threadIdx.x;
    if (i < n) {
        int r = ei_row[i], c = ei_col[i];
        g_srcP[g_offP[c] + g_rnkP[i]] = r;
        g_srcD[g_offD[r] + g_rnkD[i]] = c;
    }
}

// ---------------- fused segment-sum (half gather) + fp32 residual (+ReLU) ---
struct AggJob {
    const uint2* t;      // half rows: 32 x uint2 per row
    const float4* r;     // fp32 residual rows: 32 x float4 per row
    const int* off;
    const int* src;
    float4* out;
    int n;
    int relu;
    int nblocks;
};

__global__ void __launch_bounds__(256) seg_agg2_kernel(AggJob ja, AggJob jb) {
    int b = blockIdx.x;
    bool first = (b < ja.nblocks);
    AggJob j = first ? ja : jb;
    int local = first ? b : b - ja.nblocks;
    int w = local * 8 + (threadIdx.x >> 5);
    int lane = threadIdx.x & 31;
    if (w >= j.n) return;

    int s = j.off[w], e = j.off[w + 1];
    float4 acc = j.r[w * 32 + lane];

    int i = s;
    for (; i + 2 <= e; i += 2) {
        int s0 = __ldg(j.src + i);
        int s1 = __ldg(j.src + i + 1);
        uint2 v0 = __ldg(j.t + s0 * 32 + lane);
        uint2 v1 = __ldg(j.t + s1 * 32 + lane);
        float2 a0 = __half22float2(*(__half2*)&v0.x);
        float2 a1 = __half22float2(*(__half2*)&v0.y);
        float2 b0 = __half22float2(*(__half2*)&v1.x);
        float2 b1 = __half22float2(*(__half2*)&v1.y);
        acc.x += a0.x + b0.x;
        acc.y += a0.y + b0.y;
        acc.z += a1.x + b1.x;
        acc.w += a1.y + b1.y;
    }
    if (i < e) {
        int s0 = __ldg(j.src + i);
        uint2 v0 = __ldg(j.t + s0 * 32 + lane);
        float2 a0 = __half22float2(*(__half2*)&v0.x);
        float2 a1 = __half22float2(*(__half2*)&v0.y);
        acc.x += a0.x; acc.y += a0.y; acc.z += a1.x; acc.w += a1.y;
    }
    if (j.relu) {
        acc.x = fmaxf(acc.x, 0.f);
        acc.y = fmaxf(acc.y, 0.f);
        acc.z = fmaxf(acc.z, 0.f);
        acc.w = fmaxf(acc.w, 0.f);
    }
    j.out[w * 32 + lane] = acc;
}

// ---------------- multi-job SGEMM with FFMA2 inner loop ----------------------
// C = A[N,128] @ B[128,128] (+bias), C stored fp32 or fp16 per job.
#define BM 128
#define BN 128
#define BK 16

struct GemmJob {
    const float* A;
    const float* B;
    const float* bias;
    void* C;
    int N;
    int c_half;
    int nblocks;
};
struct GemmJobs4 { GemmJob j[4]; int n; };

__global__ void __launch_bounds__(256) gemm_multi_kernel(GemmJobs4 jobs) {
    int b = blockIdx.x;
    int ji = 0, off = 0;
    while (ji < jobs.n - 1 && b >= off + jobs.j[ji].nblocks) {
        off += jobs.j[ji].nblocks;
        ji++;
    }
    GemmJob jb = jobs.j[ji];
    int m0 = (b - off) * BM;

    __shared__ float As[BK][BM + 4];
    __shared__ float Bs[BK][BN];

    int tid = threadIdx.x;
    int ty = tid >> 4;
    int tx = tid & 15;

    unsigned long long acc2[8][4];
    unsigned long long z = pack2(0.f, 0.f);
    #pragma unroll
    for (int i = 0; i < 8; i++)
        #pragma unroll
        for (int jp = 0; jp < 4; jp++) acc2[i][jp] = z;

    for (int k0 = 0; k0 < 128; k0 += BK) {
        #pragma unroll
        for (int l = 0; l < 2; l++) {
            int f = tid + l * 256;
            int row = f >> 2;
            int c4 = f & 3;
            int gr = m0 + row;
            float4 v = make_float4(0.f, 0.f, 0.f, 0.f);
            if (gr < jb.N) v = *(const float4*)(jb.A + gr * 128 + k0 + c4 * 4);
            As[c4 * 4 + 0][row] = v.x;
            As[c4 * 4 + 1][row] = v.y;
            As[c4 * 4 + 2][row] = v.z;
            As[c4 * 4 + 3][row] = v.w;
        }
        #pragma unroll
        for (int l = 0; l < 2; l++) {
            int f = tid + l * 256;
            int kr = f >> 5;
            int c4 = f & 31;
            float4 v = *(const float4*)(jb.B + (k0 + kr) * 128 + c4 * 4);
            *(float4*)(&Bs[kr][c4 * 4]) = v;
        }
        __syncthreads();

        #pragma unroll
        for (int kk = 0; kk < BK; kk++) {
            float a[8];
            *(float4*)(a)     = *(const float4*)(&As[kk][ty * 8]);
            *(float4*)(a + 4) = *(const float4*)(&As[kk][ty * 8 + 4]);
            float4 q0 = *(const float4*)(&Bs[kk][tx * 8]);
            float4 q1 = *(const float4*)(&Bs[kk][tx * 8 + 4]);
            unsigned long long bp0 = pack2(q0.x, q0.y);
            unsigned long long bp1 = pack2(q0.z, q0.w);
            unsigned long long bp2 = pack2(q1.x, q1.y);
            unsigned long long bp3 = pack2(q1.z, q1.w);
            #pragma unroll
            for (int i = 0; i < 8; i++) {
                unsigned long long ap = pack2(a[i], a[i]);
                ffma2(acc2[i][0], ap, bp0);
                ffma2(acc2[i][1], ap, bp1);
                ffma2(acc2[i][2], ap, bp2);
                ffma2(acc2[i][3], ap, bp3);
            }
        }
        __syncthreads();
    }

    float bv[8];
    #pragma unroll
    for (int j = 0; j < 8; j++) bv[j] = jb.bias ? jb.bias[tx * 8 + j] : 0.f;

    #pragma unroll
    for (int i = 0; i < 8; i++) {
        int gr = m0 + ty * 8 + i;
        if (gr >= jb.N) continue;
        float v[8];
        #pragma unroll
        for (int jp = 0; jp < 4; jp++) {
            float2 u = unpack2(acc2[i][jp]);
            v[jp * 2] = u.x + bv[jp * 2];
            v[jp * 2 + 1] = u.y + bv[jp * 2 + 1];
        }
        if (jb.c_half) {
            __half2 h0 = __floats2half2_rn(v[0], v[1]);
            __half2 h1 = __floats2half2_rn(v[2], v[3]);
            __half2 h2 = __floats2half2_rn(v[4], v[5]);
            __half2 h3 = __floats2half2_rn(v[6], v[7]);
            uint4 o;
            o.x = *(unsigned*)&h0; o.y = *(unsigned*)&h1;
            o.z = *(unsigned*)&h2; o.w = *(unsigned*)&h3;
            *(uint4*)((__half*)jb.C + gr * 128 + tx * 8) = o;
        } else {
            float4 o0 = make_float4(v[0], v[1], v[2], v[3]);
            float4 o1 = make_float4(v[4], v[5], v[6], v[7]);
            *(float4*)((float*)jb.C + gr * 128 + tx * 8) = o0;
            *(float4*)((float*)jb.C + gr * 128 + tx * 8 + 4) = o1;
        }
    }
}

// ---------------- decoder: out[l] = relu(uD[r]+uP[c]+bd1) . Wd2 + bd2 --------
__global__ void __launch_bounds__(256) decoder_kernel(
    const uint2* __restrict__ uD, const uint2* __restrict__ uP,
    const int* __restrict__ el_row, const int* __restrict__ el_col,
    const float4* __restrict__ bd1, const float4* __restrict__ w2v,
    const float* __restrict__ bd2, float* __restrict__ out, int L)
{
    int w = (blockIdx.x * blockDim.x + threadIdx.x) >> 5;
    int lane = threadIdx.x & 31;
    if (w >= L) return;

    int r = __ldg(el_row + w);
    int c = __ldg(el_col + w);
    uint2 va = __ldg(uD + r * 32 + lane);
    uint2 vb = __ldg(uP + c * 32 + lane);
    float4 bb = __ldg(bd1 + lane);
    float4 w2 = __ldg(w2v + lane);

    float2 a0 = __half22float2(*(__half2*)&va.x);
    float2 a1 = __half22float2(*(__half2*)&va.y);
    float2 b0 = __half22float2(*(__half2*)&vb.x);
    float2 b1 = __half22float2(*(__half2*)&vb.y);

    float h0 = fmaxf(a0.x + b0.x + bb.x, 0.f);
    float h1 = fmaxf(a0.y + b0.y + bb.y, 0.f);
    float h2 = fmaxf(a1.x + b1.x + bb.z, 0.f);
    float h3 = fmaxf(a1.y + b1.y + bb.w, 0.f);

    float p = h0 * w2.x + h1 * w2.y + h2 * w2.z + h3 * w2.w;
    #pragma unroll
    for (int o = 16; o; o >>= 1) p += __shfl_down_sync(0xFFFFFFFFu, p, o);
    if (lane == 0) out[w] = p + __ldg(bd2);
}

// ---------------- launch ------------------------------------------------------
extern "C" void kernel_launch(void* const* d_in, const int* in_sizes, int n_in,
                              void* d_out, int out_size)
{
    const float* x_drug = (const float*)d_in[0];
    const float* x_prot = (const float*)d_in[1];
    const int*   ei_row = (const int*)d_in[2];
    const int*   ei_col = (const int*)d_in[3];
    const int*   el_row = (const int*)d_in[4];
    const int*   el_col = (const int*)d_in[5];
    const float* W1f_l = (const float*)d_in[6];
    const float* b1f   = (const float*)d_in[7];
    const float* W1f_r = (const float*)d_in[8];
    const float* W1r_l = (const float*)d_in[9];
    const float* b1r   = (const float*)d_in[10];
    const float* W1r_r = (const float*)d_in[11];
    const float* W2f_l = (const float*)d_in[12];
    const float* b2f   = (const float*)d_in[13];
    const float* W2f_r = (const float*)d_in[14];
    const float* W2r_l = (const float*)d_in[15];
    const float* b2r   = (const float*)d_in[16];
    const float* W2r_r = (const float*)d_in[17];
    const float* Wd1   = (const float*)d_in[18];
    const float* bd1   = (const float*)d_in[19];
    const float* Wd2   = (const float*)d_in[20];
    const float* bd2   = (const float*)d_in[21];

    const int nE = in_sizes[2];
    const int nL = in_sizes[4];

    float* outZd = (float*)d_out;
    float* outZp = outZd + (size_t)N_DRUG * DH;
    float* outO  = outZp + (size_t)N_PROT * DH;

    float *tD, *tP, *rD, *rP, *hD, *hP;
    cudaGetSymbolAddress((void**)&tD, g_tD);
    cudaGetSymbolAddress((void**)&tP, g_tP);
    cudaGetSymbolAddress((void**)&rD, g_rD);
    cudaGetSymbolAddress((void**)&rP, g_rP);
    cudaGetSymbolAddress((void**)&hD, g_hD);
    cudaGetSymbolAddress((void**)&hP, g_hP);
    int *offP, *offD, *srcP, *srcD;
    cudaGetSymbolAddress((void**)&offP, g_offP);
    cudaGetSymbolAddress((void**)&offD, g_offD);
    cudaGetSymbolAddress((void**)&srcP, g_srcP);
    cudaGetSymbolAddress((void**)&srcD, g_srcD);

    const int BD = (N_DRUG + BM - 1) / BM;   // 79
    const int BP = (N_PROT + BM - 1) / BM;   // 157

    // ---- CSR build ----
    zero_counts_kernel<<<(N_PROT + 255) / 256, 256>>>();
    hist_kernel<<<(nE + 255) / 256, 256>>>(ei_row, ei_col, nE);
    scan_kernel<<<2, 1024>>>();
    fill_kernel<<<(nE + 255) / 256, 256>>>(ei_row, ei_col, nE);

    // ---- layer 1 GEMMs (merged, 4 jobs) ----
    {
        GemmJobs4 js;
        js.j[0] = { x_drug, W1f_l, nullptr, tD, N_DRUG, 1, BD };  // tD(h) = x_drug@W1f_l
        js.j[1] = { x_drug, W1r_r, b1r,     rD, N_DRUG, 0, BD };  // rD = x_drug@W1r_r+b1r
        js.j[2] = { x_prot, W1r_l, nullptr, tP, N_PROT, 1, BP };  // tP(h) = x_prot@W1r_l
        js.j[3] = { x_prot, W1f_r, b1f,     rP, N_PROT, 0, BP };  // rP = x_prot@W1f_r+b1f
        js.n = 4;
        gemm_multi_kernel<<<2 * (BD + BP), 256>>>(js);
    }

    // ---- layer 1 aggregations (merged) ----
    {
        AggJob ja = { (const uint2*)tD, (const float4*)rP, offP, srcP,
                      (float4*)hP, N_PROT, 1, (N_PROT + 7) / 8 };
        AggJob jb = { (const uint2*)tP, (const float4*)rD, offD, srcD,
                      (float4*)hD, N_DRUG, 1, (N_DRUG + 7) / 8 };
        seg_agg2_kernel<<<ja.nblocks + jb.nblocks, 256>>>(ja, jb);
    }

    // ---- layer 2 GEMMs ----
    {
        GemmJobs4 js;
        js.j[0] = { hD, W2f_l, nullptr, tD, N_DRUG, 1, BD };
        js.j[1] = { hD, W2r_r, b2r,     rD, N_DRUG, 0, BD };
        js.j[2] = { hP, W2r_l, nullptr, tP, N_PROT, 1, BP };
        js.j[3] = { hP, W2f_r, b2f,     rP, N_PROT, 0, BP };
        js.n = 4;
        gemm_multi_kernel<<<2 * (BD + BP), 256>>>(js);
    }

    // ---- layer 2 aggregations ----
    {
        AggJob ja = { (const uint2*)tD, (const float4*)rP, offP, srcP,
                      (float4*)outZp, N_PROT, 0, (N_PROT + 7) / 8 };
        AggJob jb = { (const uint2*)tP, (const float4*)rD, offD, srcD,
                      (float4*)outZd, N_DRUG, 0, (N_DRUG + 7) / 8 };
        seg_agg2_kernel<<<ja.nblocks + jb.nblocks, 256>>>(ja, jb);
    }

    // ---- decoder node transforms (merged, half outputs) ----
    {
        GemmJobs4 js;
        js.j[0] = { outZd, Wd1,             nullptr, tD, N_DRUG, 1, BD };  // uD(h)
        js.j[1] = { outZp, Wd1 + 128 * 128, nullptr, tP, N_PROT, 1, BP };  // uP(h)
        js.j[2] = js.j[0];
        js.j[3] = js.j[0];
        js.n = 2;
        gemm_multi_kernel<<<BD + BP, 256>>>(js);
    }

    // ---- decoder per-edge MLP ----
    decoder_kernel<<<(nL * 32 + 255) / 256, 256>>>(
        (const uint2*)tD, (const uint2*)tP, el_row, el_col,
        (const float4*)bd1, (const float4*)Wd2, bd2, outO, nL);
}

// round 3
// speedup vs baseline: 1.4189x; 1.0292x over previous
#include <cuda_runtime.h>
#include <cuda_fp16.h>

// Problem constants
#define N_DRUG  10000
#define N_PROT  20000
#define DH      128
#define N_EDGES 1000000
#define N_LAB   500000

// ---------------- scratch (device globals) ----------------------------------
__device__ float g_tD[N_DRUG * DH];
__device__ float g_tP[N_PROT * DH];
__device__ float g_rD[N_DRUG * DH];
__device__ float g_rP[N_PROT * DH];
__device__ float g_hD[N_DRUG * DH];
__device__ float g_hP[N_PROT * DH];

__device__ int g_cntP[N_PROT];
__device__ int g_cntD[N_DRUG];
__device__ int g_offP[N_PROT + 1];
__device__ int g_offD[N_DRUG + 1];
__device__ int g_rnkP[N_EDGES];
__device__ int g_rnkD[N_EDGES];
__device__ int g_srcP[N_EDGES];
__device__ int g_srcD[N_EDGES];

// ---------------- small helpers ---------------------------------------------
__device__ __forceinline__ unsigned long long pack2(float x, float y) {
    unsigned long long r;
    asm("mov.b64 %0, {%1, %2};" : "=l"(r) : "f"(x), "f"(y));
    return r;
}
__device__ __forceinline__ float2 unpack2(unsigned long long v) {
    float2 r;
    asm("mov.b64 {%0, %1}, %2;" : "=f"(r.x), "=f"(r.y) : "l"(v));
    return r;
}
__device__ __forceinline__ void ffma2(unsigned long long& d,
                                      unsigned long long a,
                                      unsigned long long b) {
    asm("fma.rn.f32x2 %0, %1, %2, %0;" : "+l"(d) : "l"(a), "l"(b));
}
__device__ __forceinline__ unsigned smem_u32(const void* p) {
    unsigned r;
    asm("{ .reg .u64 t; cvta.to.shared.u64 t, %1; cvt.u32.u64 %0, t; }"
        : "=r"(r) : "l"(p));
    return r;
}
__device__ __forceinline__ void cp_async16(unsigned dst, const void* src) {
    asm volatile("cp.async.ca.shared.global [%0], [%1], 16;"
                 :: "r"(dst), "l"(src));
}
__device__ __forceinline__ void cp_commit() {
    asm volatile("cp.async.commit_group;");
}
__device__ __forceinline__ void cp_wait0() {
    asm volatile("cp.async.wait_group 0;");
}

// ---------------- CSR build --------------------------------------------------
__global__ void zero_counts_kernel() {
    int i = blockIdx.x * blockDim.x + threadIdx.x;
    if (i < N_PROT) g_cntP[i] = 0;
    if (i < N_DRUG) g_cntD[i] = 0;
}

__global__ void hist_kernel(const int* __restrict__ ei_row,
                            const int* __restrict__ ei_col, int n) {
    int i = blockIdx.x * blockDim.x + threadIdx.x;
    if (i < n) {
        int r = ei_row[i], c = ei_col[i];
        g_rnkP[i] = atomicAdd(&g_cntP[c], 1);
        g_rnkD[i] = atomicAdd(&g_cntD[r], 1);
    }
}

__global__ void scan_kernel() {
    const int n = (blockIdx.x == 0) ? N_PROT : N_DRUG;
    int* cnt    = (blockIdx.x == 0) ? g_cntP : g_cntD;
    int* off    = (blockIdx.x == 0) ? g_offP : g_offD;

    __shared__ int sums[1024];
    int tid = threadIdx.x;
    int chunk = (n + 1023) >> 10;
    int start = tid * chunk;
    int end = start + chunk; if (end > n) end = n;
    if (start > n) start = n;

    int s = 0;
    for (int i = start; i < end; i++) s += cnt[i];
    sums[tid] = s;
    __syncthreads();
    for (int d = 1; d < 1024; d <<= 1) {
        int v = (tid >= d) ? sums[tid - d] : 0;
        __syncthreads();
        sums[tid] += v;
        __syncthreads();
    }
    int prefix = tid ? sums[tid - 1] : 0;
    for (int i = start; i < end; i++) {
        off[i] = prefix;
        prefix += cnt[i];
    }
    if (tid == 1023) off[n] = sums[1023];
}

__global__ void fill_kernel(const int* __restrict__ ei_row,
                            const int* __restrict__ ei_col, int n) {
    int i = blockIdx.x * blockDim.x + threadIdx.x;
    if (i < n) {
        int r = ei_row[i], c = ei_col[i];
        g_srcP[g_offP[c] + g_rnkP[i]] = r;
        g_srcD[g_offD[r] + g_rnkD[i]] = c;
    }
}

// ---------------- fused segment-sum (half gather) + fp32 residual (+ReLU) ---
struct AggJob {
    const uint2* t;
    const float4* r;
    const int* off;
    const int* src;
    float4* out;
    int n;
    int relu;
    int nblocks;
};

__global__ void __launch_bounds__(256) seg_agg2_kernel(AggJob ja, AggJob jb) {
    int b = blockIdx.x;
    bool first = (b < ja.nblocks);
    AggJob j = first ? ja : jb;
    int local = first ? b : b - ja.nblocks;
    int w = local * 8 + (threadIdx.x >> 5);
    int lane = threadIdx.x & 31;
    if (w >= j.n) return;

    int s = j.off[w], e = j.off[w + 1];
    float4 acc = j.r[w * 32 + lane];

    int i = s;
    for (; i + 2 <= e; i += 2) {
        int s0 = __ldg(j.src + i);
        int s1 = __ldg(j.src + i + 1);
        uint2 v0 = __ldg(j.t + s0 * 32 + lane);
        uint2 v1 = __ldg(j.t + s1 * 32 + lane);
        float2 a0 = __half22float2(*(__half2*)&v0.x);
        float2 a1 = __half22float2(*(__half2*)&v0.y);
        float2 b0 = __half22float2(*(__half2*)&v1.x);
        float2 b1 = __half22float2(*(__half2*)&v1.y);
        acc.x += a0.x + b0.x;
        acc.y += a0.y + b0.y;
        acc.z += a1.x + b1.x;
        acc.w += a1.y + b1.y;
    }
    if (i < e) {
        int s0 = __ldg(j.src + i);
        uint2 v0 = __ldg(j.t + s0 * 32 + lane);
        float2 a0 = __half22float2(*(__half2*)&v0.x);
        float2 a1 = __half22float2(*(__half2*)&v0.y);
        acc.x += a0.x; acc.y += a0.y; acc.z += a1.x; acc.w += a1.y;
    }
    if (j.relu) {
        acc.x = fmaxf(acc.x, 0.f);
        acc.y = fmaxf(acc.y, 0.f);
        acc.z = fmaxf(acc.z, 0.f);
        acc.w = fmaxf(acc.w, 0.f);
    }
    j.out[w * 32 + lane] = acc;
}

// ---------------- pipelined multi-job SGEMM (BK=32, 2-stage, cp.async B) ----
#define BM 128
#define BN 128
#define BK 32
#define AS_STR 132                       // padded k-major A stride
#define A_STAGE (BK * AS_STR)            // floats per A stage
#define B_STAGE (BK * BN)                // floats per B stage
#define SMEM_FLOATS (2 * A_STAGE + 2 * B_STAGE)

struct GemmJob {
    const float* A;
    const float* B;
    const float* bias;
    void* C;
    int N;
    int c_half;
    int nblocks;
};
struct GemmJobs4 { GemmJob j[4]; int n; };

__global__ void __launch_bounds__(256, 2) gemm_multi_kernel(GemmJobs4 jobs) {
    extern __shared__ float smem[];
    float* As = smem;                    // [2][BK][AS_STR]
    float* Bs = smem + 2 * A_STAGE;      // [2][BK][BN]

    int b = blockIdx.x;
    int ji = 0, off = 0;
    while (ji < jobs.n - 1 && b >= off + jobs.j[ji].nblocks) {
        off += jobs.j[ji].nblocks;
        ji++;
    }
    GemmJob jb = jobs.j[ji];
    int m0 = (b - off) * BM;

    int tid = threadIdx.x;
    int ty = tid >> 4;
    int tx = tid & 15;

    // A-load mapping: 4 float4 per thread covering 128x32 tile
    int a_row[4], a_c4[4];
    #pragma unroll
    for (int l = 0; l < 4; l++) {
        int f = tid + l * 256;
        a_row[l] = f >> 3;        // 0..127
        a_c4[l] = f & 7;          // 0..7 -> col = c4*4
    }
    // B cp.async mapping: 4 x 16B per thread covering 32x128 tile
    int b_kr[4], b_c4[4];
    #pragma unroll
    for (int l = 0; l < 4; l++) {
        int f = tid + l * 256;
        b_kr[l] = f >> 5;         // 0..31
        b_c4[l] = f & 31;         // 0..31 -> col = c4*4
    }

    unsigned long long acc2[8][4];
    unsigned long long z = pack2(0.f, 0.f);
    #pragma unroll
    for (int i = 0; i < 8; i++)
        #pragma unroll
        for (int jp = 0; jp < 4; jp++) acc2[i][jp] = z;

    // ---- prologue: tile 0 into stage 0 ----
    float4 av[4];
    #pragma unroll
    for (int l = 0; l < 4; l++) {
        int gr = m0 + a_row[l];
        av[l] = make_float4(0.f, 0.f, 0.f, 0.f);
        if (gr < jb.N) av[l] = *(const float4*)(jb.A + gr * 128 + a_c4[l] * 4);
    }
    #pragma unroll
    for (int l = 0; l < 4; l++) {
        unsigned dst = smem_u32(&Bs[b_kr[l] * BN + b_c4[l] * 4]);
        cp_async16(dst, jb.B + b_kr[l] * 128 + b_c4[l] * 4);
    }
    cp_commit();
    #pragma unroll
    for (int l = 0; l < 4; l++) {
        float* ap = &As[(a_c4[l] * 4) * AS_STR + a_row[l]];
        ap[0 * AS_STR] = av[l].x;
        ap[1 * AS_STR] = av[l].y;
        ap[2 * AS_STR] = av[l].z;
        ap[3 * AS_STR] = av[l].w;
    }
    cp_wait0();
    __syncthreads();

    // ---- main loop over 4 K-tiles, 2-stage pipeline ----
    #pragma unroll
    for (int t = 0; t < 4; t++) {
        int cur = t & 1;
        int nxt = cur ^ 1;
        float* Ac = As + cur * A_STAGE;
        float* Bc = Bs + cur * B_STAGE;

        if (t < 3) {
            int kbase = (t + 1) * BK;
            #pragma unroll
            for (int l = 0; l < 4; l++) {
                unsigned dst = smem_u32(&Bs[nxt * B_STAGE + b_kr[l] * BN + b_c4[l] * 4]);
                cp_async16(dst, jb.B + (kbase + b_kr[l]) * 128 + b_c4[l] * 4);
            }
            cp_commit();
            #pragma unroll
            for (int l = 0; l < 4; l++) {
                int gr = m0 + a_row[l];
                av[l] = make_float4(0.f, 0.f, 0.f, 0.f);
                if (gr < jb.N)
                    av[l] = *(const float4*)(jb.A + gr * 128 + kbase + a_c4[l] * 4);
            }
        }

        #pragma unroll
        for (int kk = 0; kk < BK; kk++) {
            float a[8];
            *(float4*)(a)     = *(const float4*)(&Ac[kk * AS_STR + ty * 8]);
            *(float4*)(a + 4) = *(const float4*)(&Ac[kk * AS_STR + ty * 8 + 4]);
            float4 q0 = *(const float4*)(&Bc[kk * BN + tx * 8]);
            float4 q1 = *(const float4*)(&Bc[kk * BN + tx * 8 + 4]);
            unsigned long long bp0 = pack2(q0.x, q0.y);
            unsigned long long bp1 = pack2(q0.z, q0.w);
            unsigned long long bp2 = pack2(q1.x, q1.y);
            unsigned long long bp3 = pack2(q1.z, q1.w);
            #pragma unroll
            for (int i = 0; i < 8; i++) {
                unsigned long long ap = pack2(a[i], a[i]);
                ffma2(acc2[i][0], ap, bp0);
                ffma2(acc2[i][1], ap, bp1);
                ffma2(acc2[i][2], ap, bp2);
                ffma2(acc2[i][3], ap, bp3);
            }
        }

        if (t < 3) {
            #pragma unroll
            for (int l = 0; l < 4; l++) {
                float* ap = &As[nxt * A_STAGE + (a_c4[l] * 4) * AS_STR + a_row[l]];
                ap[0 * AS_STR] = av[l].x;
                ap[1 * AS_STR] = av[l].y;
                ap[2 * AS_STR] = av[l].z;
                ap[3 * AS_STR] = av[l].w;
            }
            cp_wait0();
        }
        __syncthreads();
    }

    float bv[8];
    #pragma unroll
    for (int j = 0; j < 8; j++) bv[j] = jb.bias ? jb.bias[tx * 8 + j] : 0.f;

    #pragma unroll
    for (int i = 0; i < 8; i++) {
        int gr = m0 + ty * 8 + i;
        if (gr >= jb.N) continue;
        float v[8];
        #pragma unroll
        for (int jp = 0; jp < 4; jp++) {
            float2 u = unpack2(acc2[i][jp]);
            v[jp * 2] = u.x + bv[jp * 2];
            v[jp * 2 + 1] = u.y + bv[jp * 2 + 1];
        }
        if (jb.c_half) {
            __half2 h0 = __floats2half2_rn(v[0], v[1]);
            __half2 h1 = __floats2half2_rn(v[2], v[3]);
            __half2 h2 = __floats2half2_rn(v[4], v[5]);
            __half2 h3 = __floats2half2_rn(v[6], v[7]);
            uint4 o;
            o.x = *(unsigned*)&h0; o.y = *(unsigned*)&h1;
            o.z = *(unsigned*)&h2; o.w = *(unsigned*)&h3;
            *(uint4*)((__half*)jb.C + gr * 128 + tx * 8) = o;
        } else {
            float4 o0 = make_float4(v[0], v[1], v[2], v[3]);
            float4 o1 = make_float4(v[4], v[5], v[6], v[7]);
            *(float4*)((float*)jb.C + gr * 128 + tx * 8) = o0;
            *(float4*)((float*)jb.C + gr * 128 + tx * 8 + 4) = o1;
        }
    }
}

// ---------------- decoder -----------------------------------------------------
__global__ void __launch_bounds__(256) decoder_kernel(
    const uint2* __restrict__ uD, const uint2* __restrict__ uP,
    const int* __restrict__ el_row, const int* __restrict__ el_col,
    const float4* __restrict__ bd1, const float4* __restrict__ w2v,
    const float* __restrict__ bd2, float* __restrict__ out, int L)
{
    int w = (blockIdx.x * blockDim.x + threadIdx.x) >> 5;
    int lane = threadIdx.x & 31;
    if (w >= L) return;

    int r = __ldg(el_row + w);
    int c = __ldg(el_col + w);
    uint2 va = __ldg(uD + r * 32 + lane);
    uint2 vb = __ldg(uP + c * 32 + lane);
    float4 bb = __ldg(bd1 + lane);
    float4 w2 = __ldg(w2v + lane);

    float2 a0 = __half22float2(*(__half2*)&va.x);
    float2 a1 = __half22float2(*(__half2*)&va.y);
    float2 b0 = __half22float2(*(__half2*)&vb.x);
    float2 b1 = __half22float2(*(__half2*)&vb.y);

    float h0 = fmaxf(a0.x + b0.x + bb.x, 0.f);
    float h1 = fmaxf(a0.y + b0.y + bb.y, 0.f);
    float h2 = fmaxf(a1.x + b1.x + bb.z, 0.f);
    float h3 = fmaxf(a1.y + b1.y + bb.w, 0.f);

    float p = h0 * w2.x + h1 * w2.y + h2 * w2.z + h3 * w2.w;
    #pragma unroll
    for (int o = 16; o; o >>= 1) p += __shfl_down_sync(0xFFFFFFFFu, p, o);
    if (lane == 0) out[w] = p + __ldg(bd2);
}

// ---------------- launch ------------------------------------------------------
extern "C" void kernel_launch(void* const* d_in, const int* in_sizes, int n_in,
                              void* d_out, int out_size)
{
    const float* x_drug = (const float*)d_in[0];
    const float* x_prot = (const float*)d_in[1];
    const int*   ei_row = (const int*)d_in[2];
    const int*   ei_col = (const int*)d_in[3];
    const int*   el_row = (const int*)d_in[4];
    const int*   el_col = (const int*)d_in[5];
    const float* W1f_l = (const float*)d_in[6];
    const float* b1f   = (const float*)d_in[7];
    const float* W1f_r = (const float*)d_in[8];
    const float* W1r_l = (const float*)d_in[9];
    const float* b1r   = (const float*)d_in[10];
    const float* W1r_r = (const float*)d_in[11];
    const float* W2f_l = (const float*)d_in[12];
    const float* b2f   = (const float*)d_in[13];
    const float* W2f_r = (const float*)d_in[14];
    const float* W2r_l = (const float*)d_in[15];
    const float* b2r   = (const float*)d_in[16];
    const float* W2r_r = (const float*)d_in[17];
    const float* Wd1   = (const float*)d_in[18];
    const float* bd1   = (const float*)d_in[19];
    const float* Wd2   = (const float*)d_in[20];
    const float* bd2   = (const float*)d_in[21];

    const int nE = in_sizes[2];
    const int nL = in_sizes[4];

    float* outZd = (float*)d_out;
    float* outZp = outZd + (size_t)N_DRUG * DH;
    float* outO  = outZp + (size_t)N_PROT * DH;

    float *tD, *tP, *rD, *rP, *hD, *hP;
    cudaGetSymbolAddress((void**)&tD, g_tD);
    cudaGetSymbolAddress((void**)&tP, g_tP);
    cudaGetSymbolAddress((void**)&rD, g_rD);
    cudaGetSymbolAddress((void**)&rP, g_rP);
    cudaGetSymbolAddress((void**)&hD, g_hD);
    cudaGetSymbolAddress((void**)&hP, g_hP);
    int *offP, *offD, *srcP, *srcD;
    cudaGetSymbolAddress((void**)&offP, g_offP);
    cudaGetSymbolAddress((void**)&offD, g_offD);
    cudaGetSymbolAddress((void**)&srcP, g_srcP);
    cudaGetSymbolAddress((void**)&srcD, g_srcD);

    const int BD = (N_DRUG + BM - 1) / BM;   // 79
    const int BP = (N_PROT + BM - 1) / BM;   // 157
    const int smem_bytes = SMEM_FLOATS * 4;  // ~66.5 KB

    static int smem_set = 0;
    if (!smem_set) {
        cudaFuncSetAttribute(gemm_multi_kernel,
                             cudaFuncAttributeMaxDynamicSharedMemorySize,
                             smem_bytes);
        smem_set = 1;
    }

    // ---- CSR build ----
    zero_counts_kernel<<<(N_PROT + 255) / 256, 256>>>();
    hist_kernel<<<(nE + 255) / 256, 256>>>(ei_row, ei_col, nE);
    scan_kernel<<<2, 1024>>>();
    fill_kernel<<<(nE + 255) / 256, 256>>>(ei_row, ei_col, nE);

    // ---- layer 1 GEMMs ----
    {
        GemmJobs4 js;
        js.j[0] = { x_drug, W1f_l, nullptr, tD, N_DRUG, 1, BD };
        js.j[1] = { x_drug, W1r_r, b1r,     rD, N_DRUG, 0, BD };
        js.j[2] = { x_prot, W1r_l, nullptr, tP, N_PROT, 1, BP };
        js.j[3] = { x_prot, W1f_r, b1f,     rP, N_PROT, 0, BP };
        js.n = 4;
        gemm_multi_kernel<<<2 * (BD + BP), 256, smem_bytes>>>(js);
    }

    // ---- layer 1 aggregations ----
    {
        AggJob ja = { (const uint2*)tD, (const float4*)rP, offP, srcP,
                      (float4*)hP, N_PROT, 1, (N_PROT + 7) / 8 };
        AggJob jb = { (const uint2*)tP, (const float4*)rD, offD, srcD,
                      (float4*)hD, N_DRUG, 1, (N_DRUG + 7) / 8 };
        seg_agg2_kernel<<<ja.nblocks + jb.nblocks, 256>>>(ja, jb);
    }

    // ---- layer 2 GEMMs ----
    {
        GemmJobs4 js;
        js.j[0] = { hD, W2f_l, nullptr, tD, N_DRUG, 1, BD };
        js.j[1] = { hD, W2r_r, b2r,     rD, N_DRUG, 0, BD };
        js.j[2] = { hP, W2r_l, nullptr, tP, N_PROT, 1, BP };
        js.j[3] = { hP, W2f_r, b2f,     rP, N_PROT, 0, BP };
        js.n = 4;
        gemm_multi_kernel<<<2 * (BD + BP), 256, smem_bytes>>>(js);
    }

    // ---- layer 2 aggregations ----
    {
        AggJob ja = { (const uint2*)tD, (const float4*)rP, offP, srcP,
                      (float4*)outZp, N_PROT, 0, (N_PROT + 7) / 8 };
        AggJob jb = { (const uint2*)tP, (const float4*)rD, offD, srcD,
                      (float4*)outZd, N_DRUG, 0, (N_DRUG + 7) / 8 };
        seg_agg2_kernel<<<ja.nblocks + jb.nblocks, 256>>>(ja, jb);
    }

    // ---- decoder node transforms ----
    {
        GemmJobs4 js;
        js.j[0] = { outZd, Wd1,             nullptr, tD, N_DRUG, 1, BD };
        js.j[1] = { outZp, Wd1 + 128 * 128, nullptr, tP, N_PROT, 1, BP };
        js.j[2] = js.j[0];
        js.j[3] = js.j[0];
        js.n = 2;
        gemm_multi_kernel<<<BD + BP, 256, smem_bytes>>>(js);
    }

    // ---- decoder per-edge MLP ----
    decoder_kernel<<<(nL * 32 + 255) / 256, 256>>>(
        (const uint2*)tD, (const uint2*)tP, el_row, el_col,
        (const float4*)bd1, (const float4*)Wd2, bd2, outO, nL);
}

// round 4
// speedup vs baseline: 1.4822x; 1.0446x over previous
#include <cuda_runtime.h>
#include <cuda_fp16.h>

// Problem constants
#define N_DRUG  10000
#define N_PROT  20000
#define DH      128
#define N_EDGES 1000000
#define N_LAB   500000

// ---------------- scratch (device globals) ----------------------------------
__device__ float g_tD[N_DRUG * DH];
__device__ float g_tP[N_PROT * DH];
__device__ float g_rD[N_DRUG * DH];
__device__ float g_rP[N_PROT * DH];
__device__ float g_hD[N_DRUG * DH];
__device__ float g_hP[N_PROT * DH];

__device__ int g_cntP[N_PROT];
__device__ int g_cntD[N_DRUG];
__device__ int g_offP[N_PROT + 1];
__device__ int g_offD[N_DRUG + 1];
__device__ int g_rnkP[N_EDGES];
__device__ int g_rnkD[N_EDGES];
__device__ int g_srcP[N_EDGES];
__device__ int g_srcD[N_EDGES];

// ---------------- small helpers ---------------------------------------------
__device__ __forceinline__ unsigned long long pack2(float x, float y) {
    unsigned long long r;
    asm("mov.b64 %0, {%1, %2};" : "=l"(r) : "f"(x), "f"(y));
    return r;
}
__device__ __forceinline__ float2 unpack2(unsigned long long v) {
    float2 r;
    asm("mov.b64 {%0, %1}, %2;" : "=f"(r.x), "=f"(r.y) : "l"(v));
    return r;
}
__device__ __forceinline__ void ffma2(unsigned long long& d,
                                      unsigned long long a,
                                      unsigned long long b) {
    asm("fma.rn.f32x2 %0, %1, %2, %0;" : "+l"(d) : "l"(a), "l"(b));
}
__device__ __forceinline__ unsigned smem_u32(const void* p) {
    unsigned r;
    asm("{ .reg .u64 t; cvta.to.shared.u64 t, %1; cvt.u32.u64 %0, t; }"
        : "=r"(r) : "l"(p));
    return r;
}
__device__ __forceinline__ void cp_async16(unsigned dst, const void* src) {
    asm volatile("cp.async.ca.shared.global [%0], [%1], 16;"
                 :: "r"(dst), "l"(src));
}
__device__ __forceinline__ void cp_commit() {
    asm volatile("cp.async.commit_group;");
}
__device__ __forceinline__ void cp_wait0() {
    asm volatile("cp.async.wait_group 0;");
}

// ---------------- CSR build --------------------------------------------------
__global__ void zero_counts_kernel() {
    int i = blockIdx.x * blockDim.x + threadIdx.x;
    if (i < N_PROT) g_cntP[i] = 0;
    if (i < N_DRUG) g_cntD[i] = 0;
}

__global__ void hist_kernel(const int* __restrict__ ei_row,
                            const int* __restrict__ ei_col, int n) {
    int i = blockIdx.x * blockDim.x + threadIdx.x;
    if (i < n) {
        int r = ei_row[i], c = ei_col[i];
        g_rnkP[i] = atomicAdd(&g_cntP[c], 1);
        g_rnkD[i] = atomicAdd(&g_cntD[r], 1);
    }
}

__global__ void scan_kernel() {
    const int n = (blockIdx.x == 0) ? N_PROT : N_DRUG;
    int* cnt    = (blockIdx.x == 0) ? g_cntP : g_cntD;
    int* off    = (blockIdx.x == 0) ? g_offP : g_offD;

    __shared__ int sums[1024];
    int tid = threadIdx.x;
    int chunk = (n + 1023) >> 10;
    int start = tid * chunk;
    int end = start + chunk; if (end > n) end = n;
    if (start > n) start = n;

    int s = 0;
    for (int i = start; i < end; i++) s += cnt[i];
    sums[tid] = s;
    __syncthreads();
    for (int d = 1; d < 1024; d <<= 1) {
        int v = (tid >= d) ? sums[tid - d] : 0;
        __syncthreads();
        sums[tid] += v;
        __syncthreads();
    }
    int prefix = tid ? sums[tid - 1] : 0;
    for (int i = start; i < end; i++) {
        off[i] = prefix;
        prefix += cnt[i];
    }
    if (tid == 1023) off[n] = sums[1023];
}

__global__ void fill_kernel(const int* __restrict__ ei_row,
                            const int* __restrict__ ei_col, int n) {
    int i = blockIdx.x * blockDim.x + threadIdx.x;
    if (i < n) {
        int r = ei_row[i], c = ei_col[i];
        g_srcP[g_offP[c] + g_rnkP[i]] = r;
        g_srcD[g_offD[r] + g_rnkD[i]] = c;
    }
}

// ---------------- fused segment-sum (half gather) + fp32 residual (+ReLU) ---
struct AggJob {
    const uint2* t;
    const float4* r;
    const int* off;
    const int* src;
    float4* out;
    int n;
    int relu;
    int nblocks;
};

__global__ void __launch_bounds__(256) seg_agg2_kernel(AggJob ja, AggJob jb) {
    int b = blockIdx.x;
    bool first = (b < ja.nblocks);
    AggJob j = first ? ja : jb;
    int local = first ? b : b - ja.nblocks;
    int w = local * 8 + (threadIdx.x >> 5);
    int lane = threadIdx.x & 31;
    if (w >= j.n) return;

    int s = j.off[w], e = j.off[w + 1];
    float4 acc = j.r[w * 32 + lane];

    int i = s;
    for (; i + 4 <= e; i += 4) {
        int s0 = __ldg(j.src + i);
        int s1 = __ldg(j.src + i + 1);
        int s2 = __ldg(j.src + i + 2);
        int s3 = __ldg(j.src + i + 3);
        uint2 v0 = __ldg(j.t + s0 * 32 + lane);
        uint2 v1 = __ldg(j.t + s1 * 32 + lane);
        uint2 v2 = __ldg(j.t + s2 * 32 + lane);
        uint2 v3 = __ldg(j.t + s3 * 32 + lane);
        float2 a0 = __half22float2(*(__half2*)&v0.x);
        float2 a1 = __half22float2(*(__half2*)&v0.y);
        float2 b0 = __half22float2(*(__half2*)&v1.x);
        float2 b1 = __half22float2(*(__half2*)&v1.y);
        float2 c0 = __half22float2(*(__half2*)&v2.x);
        float2 c1 = __half22float2(*(__half2*)&v2.y);
        float2 d0 = __half22float2(*(__half2*)&v3.x);
        float2 d1 = __half22float2(*(__half2*)&v3.y);
        acc.x += (a0.x + b0.x) + (c0.x + d0.x);
        acc.y += (a0.y + b0.y) + (c0.y + d0.y);
        acc.z += (a1.x + b1.x) + (c1.x + d1.x);
        acc.w += (a1.y + b1.y) + (c1.y + d1.y);
    }
    for (; i < e; i++) {
        int s0 = __ldg(j.src + i);
        uint2 v0 = __ldg(j.t + s0 * 32 + lane);
        float2 a0 = __half22float2(*(__half2*)&v0.x);
        float2 a1 = __half22float2(*(__half2*)&v0.y);
        acc.x += a0.x; acc.y += a0.y; acc.z += a1.x; acc.w += a1.y;
    }
    if (j.relu) {
        acc.x = fmaxf(acc.x, 0.f);
        acc.y = fmaxf(acc.y, 0.f);
        acc.z = fmaxf(acc.z, 0.f);
        acc.w = fmaxf(acc.w, 0.f);
    }
    j.out[w * 32 + lane] = acc;
}

// ---------------- pipelined multi-job SGEMM (BK=32, 2-stage, cp.async B) ----
#define BM 128
#define BN 128
#define BK 32
#define AS_STR 132
#define A_STAGE (BK * AS_STR)
#define B_STAGE (BK * BN)
#define SMEM_FLOATS (2 * A_STAGE + 2 * B_STAGE)

struct GemmJob {
    const float* A;
    const float* B;
    const float* bias;
    void* C;
    int N;
    int c_half;
    int nblocks;
};
struct GemmJobs4 { GemmJob j[4]; int n; };

__global__ void __launch_bounds__(256, 2) gemm_multi_kernel(GemmJobs4 jobs) {
    extern __shared__ float smem[];
    float* As = smem;
    float* Bs = smem + 2 * A_STAGE;

    int b = blockIdx.x;
    int ji = 0, off = 0;
    while (ji < jobs.n - 1 && b >= off + jobs.j[ji].nblocks) {
        off += jobs.j[ji].nblocks;
        ji++;
    }
    GemmJob jb = jobs.j[ji];
    int m0 = (b - off) * BM;

    int tid = threadIdx.x;
    int ty = tid >> 4;
    int tx = tid & 15;

    int a_row[4], a_c4[4];
    #pragma unroll
    for (int l = 0; l < 4; l++) {
        int f = tid + l * 256;
        a_row[l] = f >> 3;
        a_c4[l] = f & 7;
    }
    int b_kr[4], b_c4[4];
    #pragma unroll
    for (int l = 0; l < 4; l++) {
        int f = tid + l * 256;
        b_kr[l] = f >> 5;
        b_c4[l] = f & 31;
    }

    unsigned long long acc2[8][4];
    unsigned long long z = pack2(0.f, 0.f);
    #pragma unroll
    for (int i = 0; i < 8; i++)
        #pragma unroll
        for (int jp = 0; jp < 4; jp++) acc2[i][jp] = z;

    float4 av[4];
    #pragma unroll
    for (int l = 0; l < 4; l++) {
        int gr = m0 + a_row[l];
        av[l] = make_float4(0.f, 0.f, 0.f, 0.f);
        if (gr < jb.N) av[l] = *(const float4*)(jb.A + gr * 128 + a_c4[l] * 4);
    }
    #pragma unroll
    for (int l = 0; l < 4; l++) {
        unsigned dst = smem_u32(&Bs[b_kr[l] * BN + b_c4[l] * 4]);
        cp_async16(dst, jb.B + b_kr[l] * 128 + b_c4[l] * 4);
    }
    cp_commit();
    #pragma unroll
    for (int l = 0; l < 4; l++) {
        float* ap = &As[(a_c4[l] * 4) * AS_STR + a_row[l]];
        ap[0 * AS_STR] = av[l].x;
        ap[1 * AS_STR] = av[l].y;
        ap[2 * AS_STR] = av[l].z;
        ap[3 * AS_STR] = av[l].w;
    }
    cp_wait0();
    __syncthreads();

    #pragma unroll
    for (int t = 0; t < 4; t++) {
        int cur = t & 1;
        int nxt = cur ^ 1;
        float* Ac = As + cur * A_STAGE;
        float* Bc = Bs + cur * B_STAGE;

        if (t < 3) {
            int kbase = (t + 1) * BK;
            #pragma unroll
            for (int l = 0; l < 4; l++) {
                unsigned dst = smem_u32(&Bs[nxt * B_STAGE + b_kr[l] * BN + b_c4[l] * 4]);
                cp_async16(dst, jb.B + (kbase + b_kr[l]) * 128 + b_c4[l] * 4);
            }
            cp_commit();
            #pragma unroll
            for (int l = 0; l < 4; l++) {
                int gr = m0 + a_row[l];
                av[l] = make_float4(0.f, 0.f, 0.f, 0.f);
                if (gr < jb.N)
                    av[l] = *(const float4*)(jb.A + gr * 128 + kbase + a_c4[l] * 4);
            }
        }

        #pragma unroll
        for (int kk = 0; kk < BK; kk++) {
            float a[8];
            *(float4*)(a)     = *(const float4*)(&Ac[kk * AS_STR + ty * 8]);
            *(float4*)(a + 4) = *(const float4*)(&Ac[kk * AS_STR + ty * 8 + 4]);
            float4 q0 = *(const float4*)(&Bc[kk * BN + tx * 8]);
            float4 q1 = *(const float4*)(&Bc[kk * BN + tx * 8 + 4]);
            unsigned long long bp0 = pack2(q0.x, q0.y);
            unsigned long long bp1 = pack2(q0.z, q0.w);
            unsigned long long bp2 = pack2(q1.x, q1.y);
            unsigned long long bp3 = pack2(q1.z, q1.w);
            #pragma unroll
            for (int i = 0; i < 8; i++) {
                unsigned long long ap = pack2(a[i], a[i]);
                ffma2(acc2[i][0], ap, bp0);
                ffma2(acc2[i][1], ap, bp1);
                ffma2(acc2[i][2], ap, bp2);
                ffma2(acc2[i][3], ap, bp3);
            }
        }

        if (t < 3) {
            #pragma unroll
            for (int l = 0; l < 4; l++) {
                float* ap = &As[nxt * A_STAGE + (a_c4[l] * 4) * AS_STR + a_row[l]];
                ap[0 * AS_STR] = av[l].x;
                ap[1 * AS_STR] = av[l].y;
                ap[2 * AS_STR] = av[l].z;
                ap[3 * AS_STR] = av[l].w;
            }
            cp_wait0();
        }
        __syncthreads();
    }

    float bv[8];
    #pragma unroll
    for (int j = 0; j < 8; j++) bv[j] = jb.bias ? jb.bias[tx * 8 + j] : 0.f;

    #pragma unroll
    for (int i = 0; i < 8; i++) {
        int gr = m0 + ty * 8 + i;
        if (gr >= jb.N) continue;
        float v[8];
        #pragma unroll
        for (int jp = 0; jp < 4; jp++) {
            float2 u = unpack2(acc2[i][jp]);
            v[jp * 2] = u.x + bv[jp * 2];
            v[jp * 2 + 1] = u.y + bv[jp * 2 + 1];
        }
        if (jb.c_half) {
            __half2 h0 = __floats2half2_rn(v[0], v[1]);
            __half2 h1 = __floats2half2_rn(v[2], v[3]);
            __half2 h2 = __floats2half2_rn(v[4], v[5]);
            __half2 h3 = __floats2half2_rn(v[6], v[7]);
            uint4 o;
            o.x = *(unsigned*)&h0; o.y = *(unsigned*)&h1;
            o.z = *(unsigned*)&h2; o.w = *(unsigned*)&h3;
            *(uint4*)((__half*)jb.C + gr * 128 + tx * 8) = o;
        } else {
            float4 o0 = make_float4(v[0], v[1], v[2], v[3]);
            float4 o1 = make_float4(v[4], v[5], v[6], v[7]);
            *(float4*)((float*)jb.C + gr * 128 + tx * 8) = o0;
            *(float4*)((float*)jb.C + gr * 128 + tx * 8 + 4) = o1;
        }
    }
}

// ---------------- decoder -----------------------------------------------------
__global__ void __launch_bounds__(256) decoder_kernel(
    const uint2* __restrict__ uD, const uint2* __restrict__ uP,
    const int* __restrict__ el_row, const int* __restrict__ el_col,
    const float4* __restrict__ bd1, const float4* __restrict__ w2v,
    const float* __restrict__ bd2, float* __restrict__ out, int L)
{
    int w = (blockIdx.x * blockDim.x + threadIdx.x) >> 5;
    int lane = threadIdx.x & 31;
    if (w >= L) return;

    int r = __ldg(el_row + w);
    int c = __ldg(el_col + w);
    uint2 va = __ldg(uD + r * 32 + lane);
    uint2 vb = __ldg(uP + c * 32 + lane);
    float4 bb = __ldg(bd1 + lane);
    float4 w2 = __ldg(w2v + lane);

    float2 a0 = __half22float2(*(__half2*)&va.x);
    float2 a1 = __half22float2(*(__half2*)&va.y);
    float2 b0 = __half22float2(*(__half2*)&vb.x);
    float2 b1 = __half22float2(*(__half2*)&vb.y);

    float h0 = fmaxf(a0.x + b0.x + bb.x, 0.f);
    float h1 = fmaxf(a0.y + b0.y + bb.y, 0.f);
    float h2 = fmaxf(a1.x + b1.x + bb.z, 0.f);
    float h3 = fmaxf(a1.y + b1.y + bb.w, 0.f);

    float p = h0 * w2.x + h1 * w2.y + h2 * w2.z + h3 * w2.w;
    #pragma unroll
    for (int o = 16; o; o >>= 1) p += __shfl_down_sync(0xFFFFFFFFu, p, o);
    if (lane == 0) out[w] = p + __ldg(bd2);
}

// ---------------- launch ------------------------------------------------------
extern "C" void kernel_launch(void* const* d_in, const int* in_sizes, int n_in,
                              void* d_out, int out_size)
{
    const float* x_drug = (const float*)d_in[0];
    const float* x_prot = (const float*)d_in[1];
    const int*   ei_row = (const int*)d_in[2];
    const int*   ei_col = (const int*)d_in[3];
    const int*   el_row = (const int*)d_in[4];
    const int*   el_col = (const int*)d_in[5];
    const float* W1f_l = (const float*)d_in[6];
    const float* b1f   = (const float*)d_in[7];
    const float* W1f_r = (const float*)d_in[8];
    const float* W1r_l = (const float*)d_in[9];
    const float* b1r   = (const float*)d_in[10];
    const float* W1r_r = (const float*)d_in[11];
    const float* W2f_l = (const float*)d_in[12];
    const float* b2f   = (const float*)d_in[13];
    const float* W2f_r = (const float*)d_in[14];
    const float* W2r_l = (const float*)d_in[15];
    const float* b2r   = (const float*)d_in[16];
    const float* W2r_r = (const float*)d_in[17];
    const float* Wd1   = (const float*)d_in[18];
    const float* bd1   = (const float*)d_in[19];
    const float* Wd2   = (const float*)d_in[20];
    const float* bd2   = (const float*)d_in[21];

    const int nE = in_sizes[2];
    const int nL = in_sizes[4];

    float* outZd = (float*)d_out;
    float* outZp = outZd + (size_t)N_DRUG * DH;
    float* outO  = outZp + (size_t)N_PROT * DH;

    float *tD, *tP, *rD, *rP, *hD, *hP;
    cudaGetSymbolAddress((void**)&tD, g_tD);
    cudaGetSymbolAddress((void**)&tP, g_tP);
    cudaGetSymbolAddress((void**)&rD, g_rD);
    cudaGetSymbolAddress((void**)&rP, g_rP);
    cudaGetSymbolAddress((void**)&hD, g_hD);
    cudaGetSymbolAddress((void**)&hP, g_hP);
    int *offP, *offD, *srcP, *srcD;
    cudaGetSymbolAddress((void**)&offP, g_offP);
    cudaGetSymbolAddress((void**)&offD, g_offD);
    cudaGetSymbolAddress((void**)&srcP, g_srcP);
    cudaGetSymbolAddress((void**)&srcD, g_srcD);

    const int BD = (N_DRUG + BM - 1) / BM;   // 79
    const int BP = (N_PROT + BM - 1) / BM;   // 157
    const int smem_bytes = SMEM_FLOATS * 4;  // ~66.5 KB

    // one-time host-side setup (first call = correctness run, not captured)
    static cudaStream_t s_csr = nullptr;
    static cudaEvent_t evFork = nullptr, evJoin = nullptr;
    if (!s_csr) {
        cudaFuncSetAttribute(gemm_multi_kernel,
                             cudaFuncAttributeMaxDynamicSharedMemorySize,
                             smem_bytes);
        cudaStreamCreateWithFlags(&s_csr, cudaStreamNonBlocking);
        cudaEventCreateWithFlags(&evFork, cudaEventDisableTiming);
        cudaEventCreateWithFlags(&evJoin, cudaEventDisableTiming);
    }

    // ---- fork: CSR build on side stream, concurrent with layer-1 GEMMs ----
    cudaEventRecord(evFork, 0);
    cudaStreamWaitEvent(s_csr, evFork, 0);

    zero_counts_kernel<<<(N_PROT + 255) / 256, 256, 0, s_csr>>>();
    hist_kernel<<<(nE + 255) / 256, 256, 0, s_csr>>>(ei_row, ei_col, nE);
    scan_kernel<<<2, 1024, 0, s_csr>>>();
    fill_kernel<<<(nE + 255) / 256, 256, 0, s_csr>>>(ei_row, ei_col, nE);
    cudaEventRecord(evJoin, s_csr);

    // ---- layer 1 GEMMs (default stream, concurrent with CSR) ----
    {
        GemmJobs4 js;
        js.j[0] = { x_drug, W1f_l, nullptr, tD, N_DRUG, 1, BD };
        js.j[1] = { x_drug, W1r_r, b1r,     rD, N_DRUG, 0, BD };
        js.j[2] = { x_prot, W1r_l, nullptr, tP, N_PROT, 1, BP };
        js.j[3] = { x_prot, W1f_r, b1f,     rP, N_PROT, 0, BP };
        js.n = 4;
        gemm_multi_kernel<<<2 * (BD + BP), 256, smem_bytes>>>(js);
    }

    // ---- join before first aggregation ----
    cudaStreamWaitEvent(0, evJoin, 0);

    // ---- layer 1 aggregations ----
    {
        AggJob ja = { (const uint2*)tD, (const float4*)rP, offP, srcP,
                      (float4*)hP, N_PROT, 1, (N_PROT + 7) / 8 };
        AggJob jb = { (const uint2*)tP, (const float4*)rD, offD, srcD,
                      (float4*)hD, N_DRUG, 1, (N_DRUG + 7) / 8 };
        seg_agg2_kernel<<<ja.nblocks + jb.nblocks, 256>>>(ja, jb);
    }

    // ---- layer 2 GEMMs ----
    {
        GemmJobs4 js;
        js.j[0] = { hD, W2f_l, nullptr, tD, N_DRUG, 1, BD };
        js.j[1] = { hD, W2r_r, b2r,     rD, N_DRUG, 0, BD };
        js.j[2] = { hP, W2r_l, nullptr, tP, N_PROT, 1, BP };
        js.j[3] = { hP, W2f_r, b2f,     rP, N_PROT, 0, BP };
        js.n = 4;
        gemm_multi_kernel<<<2 * (BD + BP), 256, smem_bytes>>>(js);
    }

    // ---- layer 2 aggregations ----
    {
        AggJob ja = { (const uint2*)tD, (const float4*)rP, offP, srcP,
                      (float4*)outZp, N_PROT, 0, (N_PROT + 7) / 8 };
        AggJob jb = { (const uint2*)tP, (const float4*)rD, offD, srcD,
                      (float4*)outZd, N_DRUG, 0, (N_DRUG + 7) / 8 };
        seg_agg2_kernel<<<ja.nblocks + jb.nblocks, 256>>>(ja, jb);
    }

    // ---- decoder node transforms ----
    {
        GemmJobs4 js;
        js.j[0] = { outZd, Wd1,             nullptr, tD, N_DRUG, 1, BD };
        js.j[1] = { outZp, Wd1 + 128 * 128, nullptr, tP, N_PROT, 1, BP };
        js.j[2] = js.j[0];
        js.j[3] = js.j[0];
        js.n = 2;
        gemm_multi_kernel<<<BD + BP, 256, smem_bytes>>>(js);
    }

    // ---- decoder per-edge MLP ----
    decoder_kernel<<<(nL * 32 + 255) / 256, 256>>>(
        (const uint2*)tD, (const uint2*)tP, el_row, el_col,
        (const float4*)bd1, (const float4*)Wd2, bd2, outO, nL);
}

// round 5
// speedup vs baseline: 1.9121x; 1.2900x over previous
#include <cuda_runtime.h>
#include <cuda_fp16.h>

// Problem constants
#define N_DRUG  10000
#define N_PROT  20000
#define DH      128
#define N_EDGES 1000000
#define N_LAB   500000

// ---------------- scratch (device globals) ----------------------------------
__device__ float g_tD[N_DRUG * DH];
__device__ float g_tP[N_PROT * DH];
__device__ float g_rD[N_DRUG * DH];
__device__ float g_rP[N_PROT * DH];
__device__ float g_hD[N_DRUG * DH];
__device__ float g_hP[N_PROT * DH];

__device__ int g_cntP[N_PROT];
__device__ int g_cntD[N_DRUG];
__device__ int g_offP[N_PROT + 1];
__device__ int g_offD[N_DRUG + 1];
__device__ int g_rnkP[N_EDGES];
__device__ int g_rnkD[N_EDGES];
__device__ int g_srcP[N_EDGES];
__device__ int g_srcD[N_EDGES];

// ---------------- small helpers ---------------------------------------------
__device__ __forceinline__ unsigned smem_u32(const void* p) {
    unsigned r;
    asm("{ .reg .u64 t; cvta.to.shared.u64 t, %1; cvt.u32.u64 %0, t; }"
        : "=r"(r) : "l"(p));
    return r;
}
__device__ __forceinline__ void ldsm_x4(unsigned* r, unsigned addr) {
    asm volatile("ldmatrix.sync.aligned.m8n8.x4.shared.b16 {%0,%1,%2,%3}, [%4];"
                 : "=r"(r[0]), "=r"(r[1]), "=r"(r[2]), "=r"(r[3]) : "r"(addr));
}
__device__ __forceinline__ void ldsm_x4_t(unsigned* r, unsigned addr) {
    asm volatile("ldmatrix.sync.aligned.m8n8.x4.trans.shared.b16 {%0,%1,%2,%3}, [%4];"
                 : "=r"(r[0]), "=r"(r[1]), "=r"(r[2]), "=r"(r[3]) : "r"(addr));
}
__device__ __forceinline__ void mma16816(float* d, const unsigned* a, const unsigned* b) {
    asm volatile("mma.sync.aligned.m16n8k16.row.col.f32.f16.f16.f32 "
                 "{%0,%1,%2,%3}, {%4,%5,%6,%7}, {%8,%9}, {%0,%1,%2,%3};"
                 : "+f"(d[0]), "+f"(d[1]), "+f"(d[2]), "+f"(d[3])
                 : "r"(a[0]), "r"(a[1]), "r"(a[2]), "r"(a[3]),
                   "r"(b[0]), "r"(b[1]));
}
__device__ __forceinline__ uint2 f4_to_h4(float4 v) {
    __half2 h01 = __floats2half2_rn(v.x, v.y);
    __half2 h23 = __floats2half2_rn(v.z, v.w);
    uint2 r;
    r.x = *(unsigned*)&h01;
    r.y = *(unsigned*)&h23;
    return r;
}

// ---------------- CSR build --------------------------------------------------
__global__ void zero_counts_kernel() {
    int i = blockIdx.x * blockDim.x + threadIdx.x;
    if (i < N_PROT) g_cntP[i] = 0;
    if (i < N_DRUG) g_cntD[i] = 0;
}

__global__ void hist_kernel(const int* __restrict__ ei_row,
                            const int* __restrict__ ei_col, int n) {
    int i = blockIdx.x * blockDim.x + threadIdx.x;
    if (i < n) {
        int r = ei_row[i], c = ei_col[i];
        g_rnkP[i] = atomicAdd(&g_cntP[c], 1);
        g_rnkD[i] = atomicAdd(&g_cntD[r], 1);
    }
}

__global__ void scan_kernel() {
    const int n = (blockIdx.x == 0) ? N_PROT : N_DRUG;
    int* cnt    = (blockIdx.x == 0) ? g_cntP : g_cntD;
    int* off    = (blockIdx.x == 0) ? g_offP : g_offD;

    __shared__ int sums[1024];
    int tid = threadIdx.x;
    int chunk = (n + 1023) >> 10;
    int start = tid * chunk;
    int end = start + chunk; if (end > n) end = n;
    if (start > n) start = n;

    int s = 0;
    for (int i = start; i < end; i++) s += cnt[i];
    sums[tid] = s;
    __syncthreads();
    for (int d = 1; d < 1024; d <<= 1) {
        int v = (tid >= d) ? sums[tid - d] : 0;
        __syncthreads();
        sums[tid] += v;
        __syncthreads();
    }
    int prefix = tid ? sums[tid - 1] : 0;
    for (int i = start; i < end; i++) {
        off[i] = prefix;
        prefix += cnt[i];
    }
    if (tid == 1023) off[n] = sums[1023];
}

__global__ void fill_kernel(const int* __restrict__ ei_row,
                            const int* __restrict__ ei_col, int n) {
    int i = blockIdx.x * blockDim.x + threadIdx.x;
    if (i < n) {
        int r = ei_row[i], c = ei_col[i];
        g_srcP[g_offP[c] + g_rnkP[i]] = r;
        g_srcD[g_offD[r] + g_rnkD[i]] = c;
    }
}

// ---------------- fused segment-sum (half gather) + fp32 residual (+ReLU) ---
struct AggJob {
    const uint2* t;
    const float4* r;
    const int* off;
    const int* src;
    float4* out;
    int n;
    int relu;
    int nblocks;
};

__global__ void __launch_bounds__(256) seg_agg2_kernel(AggJob ja, AggJob jb) {
    int b = blockIdx.x;
    bool first = (b < ja.nblocks);
    AggJob j = first ? ja : jb;
    int local = first ? b : b - ja.nblocks;
    int w = local * 8 + (threadIdx.x >> 5);
    int lane = threadIdx.x & 31;
    if (w >= j.n) return;

    int s = j.off[w], e = j.off[w + 1];
    float4 acc = j.r[w * 32 + lane];

    int i = s;
    for (; i + 4 <= e; i += 4) {
        int s0 = __ldg(j.src + i);
        int s1 = __ldg(j.src + i + 1);
        int s2 = __ldg(j.src + i + 2);
        int s3 = __ldg(j.src + i + 3);
        uint2 v0 = __ldg(j.t + s0 * 32 + lane);
        uint2 v1 = __ldg(j.t + s1 * 32 + lane);
        uint2 v2 = __ldg(j.t + s2 * 32 + lane);
        uint2 v3 = __ldg(j.t + s3 * 32 + lane);
        float2 a0 = __half22float2(*(__half2*)&v0.x);
        float2 a1 = __half22float2(*(__half2*)&v0.y);
        float2 b0 = __half22float2(*(__half2*)&v1.x);
        float2 b1 = __half22float2(*(__half2*)&v1.y);
        float2 c0 = __half22float2(*(__half2*)&v2.x);
        float2 c1 = __half22float2(*(__half2*)&v2.y);
        float2 d0 = __half22float2(*(__half2*)&v3.x);
        float2 d1 = __half22float2(*(__half2*)&v3.y);
        acc.x += (a0.x + b0.x) + (c0.x + d0.x);
        acc.y += (a0.y + b0.y) + (c0.y + d0.y);
        acc.z += (a1.x + b1.x) + (c1.x + d1.x);
        acc.w += (a1.y + b1.y) + (c1.y + d1.y);
    }
    for (; i < e; i++) {
        int s0 = __ldg(j.src + i);
        uint2 v0 = __ldg(j.t + s0 * 32 + lane);
        float2 a0 = __half22float2(*(__half2*)&v0.x);
        float2 a1 = __half22float2(*(__half2*)&v0.y);
        acc.x += a0.x; acc.y += a0.y; acc.z += a1.x; acc.w += a1.y;
    }
    if (j.relu) {
        acc.x = fmaxf(acc.x, 0.f);
        acc.y = fmaxf(acc.y, 0.f);
        acc.z = fmaxf(acc.z, 0.f);
        acc.w = fmaxf(acc.w, 0.f);
    }
    j.out[w * 32 + lane] = acc;
}

// ---------------- HMMA multi-job GEMM (fp16 in, fp32 acc) -------------------
// C = A[N,128] @ B[128,128] (+bias). 128x128 block tile, BK=32, 8 warps (4Mx2N),
// warp tile 32x64 via m16n8k16. A/B converted fp32->fp16 at the smem boundary.
#define BM 128
#define BN 128
#define BK 32
#define AS_H 40                   // halves per A smem row (80B, conflict-free ldsm)
#define A_ST (BM * AS_H)          // 5120 halves / stage
#define B_ST (BK * BN)            // 4096 halves / stage

struct GemmJob {
    const float* A;
    const float* B;
    const float* bias;
    void* C;
    int N;
    int c_half;
    int nblocks;
};
struct GemmJobs4 { GemmJob j[4]; int n; };

__global__ void __launch_bounds__(256, 2) gemm_multi_kernel(GemmJobs4 jobs) {
    __shared__ __align__(16) __half As[2][A_ST];
    __shared__ __align__(16) __half Bs[2][B_ST];

    int b = blockIdx.x;
    int ji = 0, off = 0;
    while (ji < jobs.n - 1 && b >= off + jobs.j[ji].nblocks) {
        off += jobs.j[ji].nblocks;
        ji++;
    }
    GemmJob jb = jobs.j[ji];
    int m0 = (b - off) * BM;

    int tid = threadIdx.x;
    int lane = tid & 31;
    int wid = tid >> 5;
    int m0w = (wid & 3) * 32;      // warp M offset
    int n0w = (wid >> 2) * 64;     // warp N offset

    // global-load mappings (4 float4 per thread for each of A and B)
    int a_row[4], a_c4[4], b_k[4], b_c4[4];
    #pragma unroll
    for (int l = 0; l < 4; l++) {
        int f = tid + l * 256;
        a_row[l] = f >> 3;         // 0..127
        a_c4[l] = f & 7;           // 0..7
        b_k[l] = f >> 5;           // 0..31
        b_c4[l] = f & 31;          // 0..31
    }

    float acc[2][8][4];
    #pragma unroll
    for (int mi = 0; mi < 2; mi++)
        #pragma unroll
        for (int ni = 0; ni < 8; ni++)
            #pragma unroll
            for (int q = 0; q < 4; q++) acc[mi][ni][q] = 0.f;

    float4 av[4], bvv[4];
    // prologue: tile 0
    #pragma unroll
    for (int l = 0; l < 4; l++) {
        int gr = m0 + a_row[l];
        av[l] = make_float4(0.f, 0.f, 0.f, 0.f);
        if (gr < jb.N) av[l] = *(const float4*)(jb.A + gr * 128 + a_c4[l] * 4);
        bvv[l] = *(const float4*)(jb.B + b_k[l] * 128 + b_c4[l] * 4);
    }
    #pragma unroll
    for (int l = 0; l < 4; l++) {
        *(uint2*)&As[0][a_row[l] * AS_H + a_c4[l] * 4] = f4_to_h4(av[l]);
        int k = b_k[l];
        int cc = (b_c4[l] >> 1) ^ (k & 7);
        *(uint2*)&Bs[0][k * BN + cc * 8 + (b_c4[l] & 1) * 4] = f4_to_h4(bvv[l]);
    }
    __syncthreads();

    #pragma unroll
    for (int t = 0; t < 4; t++) {
        int cur = t & 1;
        int nxt = cur ^ 1;

        if (t < 3) {
            int kb = (t + 1) * BK;
            #pragma unroll
            for (int l = 0; l < 4; l++) {
                int gr = m0 + a_row[l];
                av[l] = make_float4(0.f, 0.f, 0.f, 0.f);
                if (gr < jb.N)
                    av[l] = *(const float4*)(jb.A + gr * 128 + kb + a_c4[l] * 4);
                bvv[l] = *(const float4*)(jb.B + (kb + b_k[l]) * 128 + b_c4[l] * 4);
            }
        }

        // compute current stage: 2 k-steps of 16
        #pragma unroll
        for (int ks = 0; ks < 2; ks++) {
            int k0 = ks * 16;
            unsigned afr[2][4], bfr[8][2];
            #pragma unroll
            for (int mi = 0; mi < 2; mi++) {
                unsigned addr = smem_u32(
                    &As[cur][(m0w + mi * 16 + (lane & 15)) * AS_H + k0 +
                             ((lane >> 4) & 1) * 8]);
                ldsm_x4(afr[mi], addr);
            }
            #pragma unroll
            for (int pi = 0; pi < 4; pi++) {
                int kr = k0 + (lane & 7) + ((lane >> 3) & 1) * 8;
                int nc = n0w + pi * 16 + (lane >> 4) * 8;
                int cc = (nc >> 3) ^ (kr & 7);
                unsigned addr = smem_u32(&Bs[cur][kr * BN + cc * 8]);
                ldsm_x4_t(&bfr[2 * pi][0], addr);
            }
            #pragma unroll
            for (int mi = 0; mi < 2; mi++)
                #pragma unroll
                for (int ni = 0; ni < 8; ni++)
                    mma16816(acc[mi][ni], afr[mi], bfr[ni]);
        }

        if (t < 3) {
            #pragma unroll
            for (int l = 0; l < 4; l++) {
                *(uint2*)&As[nxt][a_row[l] * AS_H + a_c4[l] * 4] = f4_to_h4(av[l]);
                int k = b_k[l];
                int cc = (b_c4[l] >> 1) ^ (k & 7);
                *(uint2*)&Bs[nxt][k * BN + cc * 8 + (b_c4[l] & 1) * 4] = f4_to_h4(bvv[l]);
            }
        }
        __syncthreads();
    }

    // epilogue
    #pragma unroll
    for (int ni = 0; ni < 8; ni++) {
        int col = n0w + ni * 8 + (lane & 3) * 2;
        float bz0 = jb.bias ? __ldg(jb.bias + col) : 0.f;
        float bz1 = jb.bias ? __ldg(jb.bias + col + 1) : 0.f;
        #pragma unroll
        for (int mi = 0; mi < 2; mi++) {
            int r0 = m0 + m0w + mi * 16 + (lane >> 2);
            int r1 = r0 + 8;
            float e0 = acc[mi][ni][0] + bz0;
            float e1 = acc[mi][ni][1] + bz1;
            float e2 = acc[mi][ni][2] + bz0;
            float e3 = acc[mi][ni][3] + bz1;
            if (jb.c_half) {
                if (r0 < jb.N) {
                    __half2 h = __floats2half2_rn(e0, e1);
                    *(__half2*)((__half*)jb.C + r0 * 128 + col) = h;
                }
                if (r1 < jb.N) {
                    __half2 h = __floats2half2_rn(e2, e3);
                    *(__half2*)((__half*)jb.C + r1 * 128 + col) = h;
                }
            } else {
                if (r0 < jb.N)
                    *(float2*)((float*)jb.C + r0 * 128 + col) = make_float2(e0, e1);
                if (r1 < jb.N)
                    *(float2*)((float*)jb.C + r1 * 128 + col) = make_float2(e2, e3);
            }
        }
    }
}

// ---------------- decoder -----------------------------------------------------
__global__ void __launch_bounds__(256) decoder_kernel(
    const uint2* __restrict__ uD, const uint2* __restrict__ uP,
    const int* __restrict__ el_row, const int* __restrict__ el_col,
    const float4* __restrict__ bd1, const float4* __restrict__ w2v,
    const float* __restrict__ bd2, float* __restrict__ out, int L)
{
    int w = (blockIdx.x * blockDim.x + threadIdx.x) >> 5;
    int lane = threadIdx.x & 31;
    if (w >= L) return;

    int r = __ldg(el_row + w);
    int c = __ldg(el_col + w);
    uint2 va = __ldg(uD + r * 32 + lane);
    uint2 vb = __ldg(uP + c * 32 + lane);
    float4 bb = __ldg(bd1 + lane);
    float4 w2 = __ldg(w2v + lane);

    float2 a0 = __half22float2(*(__half2*)&va.x);
    float2 a1 = __half22float2(*(__half2*)&va.y);
    float2 b0 = __half22float2(*(__half2*)&vb.x);
    float2 b1 = __half22float2(*(__half2*)&vb.y);

    float h0 = fmaxf(a0.x + b0.x + bb.x, 0.f);
    float h1 = fmaxf(a0.y + b0.y + bb.y, 0.f);
    float h2 = fmaxf(a1.x + b1.x + bb.z, 0.f);
    float h3 = fmaxf(a1.y + b1.y + bb.w, 0.f);

    float p = h0 * w2.x + h1 * w2.y + h2 * w2.z + h3 * w2.w;
    #pragma unroll
    for (int o = 16; o; o >>= 1) p += __shfl_down_sync(0xFFFFFFFFu, p, o);
    if (lane == 0) out[w] = p + __ldg(bd2);
}

// ---------------- launch ------------------------------------------------------
extern "C" void kernel_launch(void* const* d_in, const int* in_sizes, int n_in,
                              void* d_out, int out_size)
{
    const float* x_drug = (const float*)d_in[0];
    const float* x_prot = (const float*)d_in[1];
    const int*   ei_row = (const int*)d_in[2];
    const int*   ei_col = (const int*)d_in[3];
    const int*   el_row = (const int*)d_in[4];
    const int*   el_col = (const int*)d_in[5];
    const float* W1f_l = (const float*)d_in[6];
    const float* b1f   = (const float*)d_in[7];
    const float* W1f_r = (const float*)d_in[8];
    const float* W1r_l = (const float*)d_in[9];
    const float* b1r   = (const float*)d_in[10];
    const float* W1r_r = (const float*)d_in[11];
    const float* W2f_l = (const float*)d_in[12];
    const float* b2f   = (const float*)d_in[13];
    const float* W2f_r = (const float*)d_in[14];
    const float* W2r_l = (const float*)d_in[15];
    const float* b2r   = (const float*)d_in[16];
    const float* W2r_r = (const float*)d_in[17];
    const float* Wd1   = (const float*)d_in[18];
    const float* bd1   = (const float*)d_in[19];
    const float* Wd2   = (const float*)d_in[20];
    const float* bd2   = (const float*)d_in[21];

    const int nE = in_sizes[2];
    const int nL = in_sizes[4];

    float* outZd = (float*)d_out;
    float* outZp = outZd + (size_t)N_DRUG * DH;
    float* outO  = outZp + (size_t)N_PROT * DH;

    float *tD, *tP, *rD, *rP, *hD, *hP;
    cudaGetSymbolAddress((void**)&tD, g_tD);
    cudaGetSymbolAddress((void**)&tP, g_tP);
    cudaGetSymbolAddress((void**)&rD, g_rD);
    cudaGetSymbolAddress((void**)&rP, g_rP);
    cudaGetSymbolAddress((void**)&hD, g_hD);
    cudaGetSymbolAddress((void**)&hP, g_hP);
    int *offP, *offD, *srcP, *srcD;
    cudaGetSymbolAddress((void**)&offP, g_offP);
    cudaGetSymbolAddress((void**)&offD, g_offD);
    cudaGetSymbolAddress((void**)&srcP, g_srcP);
    cudaGetSymbolAddress((void**)&srcD, g_srcD);

    const int BD = (N_DRUG + BM - 1) / BM;   // 79
    const int BP = (N_PROT + BM - 1) / BM;   // 157

    // one-time host-side setup (first call = correctness run, not captured)
    static cudaStream_t s_csr = nullptr;
    static cudaEvent_t evFork = nullptr, evJoin = nullptr;
    if (!s_csr) {
        cudaStreamCreateWithFlags(&s_csr, cudaStreamNonBlocking);
        cudaEventCreateWithFlags(&evFork, cudaEventDisableTiming);
        cudaEventCreateWithFlags(&evJoin, cudaEventDisableTiming);
    }

    // ---- fork: CSR build on side stream, concurrent with layer-1 GEMMs ----
    cudaEventRecord(evFork, 0);
    cudaStreamWaitEvent(s_csr, evFork, 0);

    zero_counts_kernel<<<(N_PROT + 255) / 256, 256, 0, s_csr>>>();
    hist_kernel<<<(nE + 255) / 256, 256, 0, s_csr>>>(ei_row, ei_col, nE);
    scan_kernel<<<2, 1024, 0, s_csr>>>();
    fill_kernel<<<(nE + 255) / 256, 256, 0, s_csr>>>(ei_row, ei_col, nE);
    cudaEventRecord(evJoin, s_csr);

    // ---- layer 1 GEMMs (default stream, concurrent with CSR) ----
    {
        GemmJobs4 js;
        js.j[0] = { x_drug, W1f_l, nullptr, tD, N_DRUG, 1, BD };
        js.j[1] = { x_drug, W1r_r, b1r,     rD, N_DRUG, 0, BD };
        js.j[2] = { x_prot, W1r_l, nullptr, tP, N_PROT, 1, BP };
        js.j[3] = { x_prot, W1f_r, b1f,     rP, N_PROT, 0, BP };
        js.n = 4;
        gemm_multi_kernel<<<2 * (BD + BP), 256>>>(js);
    }

    // ---- join before first aggregation ----
    cudaStreamWaitEvent(0, evJoin, 0);

    // ---- layer 1 aggregations ----
    {
        AggJob ja = { (const uint2*)tD, (const float4*)rP, offP, srcP,
                      (float4*)hP, N_PROT, 1, (N_PROT + 7) / 8 };
        AggJob jb = { (const uint2*)tP, (const float4*)rD, offD, srcD,
                      (float4*)hD, N_DRUG, 1, (N_DRUG + 7) / 8 };
        seg_agg2_kernel<<<ja.nblocks + jb.nblocks, 256>>>(ja, jb);
    }

    // ---- layer 2 GEMMs ----
    {
        GemmJobs4 js;
        js.j[0] = { hD, W2f_l, nullptr, tD, N_DRUG, 1, BD };
        js.j[1] = { hD, W2r_r, b2r,     rD, N_DRUG, 0, BD };
        js.j[2] = { hP, W2r_l, nullptr, tP, N_PROT, 1, BP };
        js.j[3] = { hP, W2f_r, b2f,     rP, N_PROT, 0, BP };
        js.n = 4;
        gemm_multi_kernel<<<2 * (BD + BP), 256>>>(js);
    }

    // ---- layer 2 aggregations ----
    {
        AggJob ja = { (const uint2*)tD, (const float4*)rP, offP, srcP,
                      (float4*)outZp, N_PROT, 0, (N_PROT + 7) / 8 };
        AggJob jb = { (const uint2*)tP, (const float4*)rD, offD, srcD,
                      (float4*)outZd, N_DRUG, 0, (N_DRUG + 7) / 8 };
        seg_agg2_kernel<<<ja.nblocks + jb.nblocks, 256>>>(ja, jb);
    }

    // ---- decoder node transforms ----
    {
        GemmJobs4 js;
        js.j[0] = { outZd, Wd1,             nullptr, tD, N_DRUG, 1, BD };
        js.j[1] = { outZp, Wd1 + 128 * 128, nullptr, tP, N_PROT, 1, BP };
        js.j[2] = js.j[0];
        js.j[3] = js.j[0];
        js.n = 2;
        gemm_multi_kernel<<<BD + BP, 256>>>(js);
    }

    // ---- decoder per-edge MLP ----
    decoder_kernel<<<(nL * 32 + 255) / 256, 256>>>(
        (const uint2*)tD, (const uint2*)tP, el_row, el_col,
        (const float4*)bd1, (const float4*)Wd2, bd2, outO, nL);
}